// round 6
// baseline (speedup 1.0000x reference)
#include <cuda_runtime.h>
#include <cuda_bf16.h>
#include <math.h>
#include <stdint.h>

// Problem constants
#define BB   128
#define DD   256
#define SS   512
#define KK   50
#define HH   256
#define NROW 65536           // B*S
#define OUT_PRED   0         // 256 floats
#define OUT_ZERO   256
#define OUT_CSIM   257
#define OUT_CFAR   258
#define OUT_TPNN   259       // 3,276,800 floats (ODD offset: scalar stores only!)
#define OUT_AE     3277059

// -------- scratch (static device memory; no allocations allowed) --------
__device__ float g_tvn[DD * KK];                   // normalized topic vectors [d][k]
__device__ float g_rnorm[NROW];                    // 1/max(||x||,1e-12) per row
__device__ float g_tpnT[(size_t)KK * NROW];        // topic_prob_n transposed [k][row]
__device__ __nv_bfloat16 g_rec1o_bf[(size_t)NROW * HH]; // relu(nn@rec1) bf16
__device__ __nv_bfloat16 g_rec2T_bf[DD * HH];      // rec2 transposed [d][h] bf16
__device__ float g_hpart[4096 * HH];               // per-A2-CTA fp32 colsums
__device__ float g_rowrec[BB * DD];                // fp32 (sum_s rec1out) @ rec2
__device__ float g_aepart[1024];                   // per-kernelB-CTA ae partials
__device__ float g_topsum[KK];                     // per-concept top-32 sums
// top-k selection scratch
__device__ int   g_hist[KK * 128];
__device__ int   g_bstar[KK];
__device__ int   g_candcnt[KK];
__device__ float g_cand[(size_t)KK * NROW];

// ------------------- f32x2 helpers (sm_103a packed fp32) ----------------
__device__ __forceinline__ unsigned long long fma2(unsigned long long a,
                                                   unsigned long long b,
                                                   unsigned long long c) {
    unsigned long long d;
    asm("fma.rn.f32x2 %0, %1, %2, %3;" : "=l"(d) : "l"(a), "l"(b), "l"(c));
    return d;
}
__device__ __forceinline__ unsigned long long dup2(float x) {
    unsigned long long r;
    asm("mov.b64 %0, {%1, %1};" : "=l"(r) : "r"(__float_as_uint(x)));
    return r;
}
__device__ __forceinline__ void unpk(unsigned long long v, float& lo, float& hi) {
    uint32_t a, b;
    asm("mov.b64 {%0, %1}, %2;" : "=r"(a), "=r"(b) : "l"(v));
    lo = __uint_as_float(a);
    hi = __uint_as_float(b);
}

// =========== prep2: tv_n + concept_far + zero scratch + rec2 bf16 T =====
__global__ void prep2(const float* __restrict__ tv, const float* __restrict__ rec2,
                      float* __restrict__ out) {
    int t = threadIdx.x;                 // 256 threads
    if (blockIdx.x > 0) {                // convT part: blocks 1..256 -> d
        int d = blockIdx.x - 1;
        g_rec2T_bf[d * HH + t] = __float2bfloat16(rec2[t * DD + d]);
        return;
    }
    __shared__ float cinv[64];
    __shared__ float sd[DD];
    for (int i = t; i < KK * 128; i += 256) g_hist[i] = 0;
    if (t < KK) g_candcnt[t] = 0;
    if (t < KK) {
        float s = 0.f;
        for (int d = 0; d < DD; d++) { float v = tv[d * KK + t]; s += v * v; }
        cinv[t] = 1.0f / fmaxf(sqrtf(s), 1e-12f);
    }
    __syncthreads();
    {   // thread t == d
        float sum = 0.f;
        for (int k = 0; k < KK; k++) {
            float v = tv[t * KK + k] * cinv[k];
            g_tvn[t * KK + k] = v;
            sum += v;
        }
        sd[t] = sum;
    }
    __syncthreads();
    if (t == 0) {
        float g = 0.f;
        for (int d = 0; d < DD; d++) g += sd[d] * sd[d];
        out[OUT_CFAR] = (g - (float)KK) / (float)(KK * KK);
        out[OUT_ZERO] = 0.0f;
    }
}

// ============ A1: streaming topic path (f32x2, per-thread rows) =========
// grid 256 (b, s-half), 256 threads, 1 s-row per thread
#define A1_SMEM ((256 * 52) * 4 + KK * 128 * 4)

__global__ void __launch_bounds__(256, 2) kernelA1(const float* __restrict__ fin,
                                                   float* __restrict__ out) {
    extern __shared__ float sm[];
    float* tvs = sm;                     // [256 d][52 k] padded (float2 pairs)
    int*   hloc = (int*)(sm + 256 * 52); // [50][128]

    int t = threadIdx.x;
    int cid = blockIdx.x;
    int b = cid >> 1, half = cid & 1;
    int s = half * 256 + t;
    int gRow = b * SS + s;
    const float* fb = fin + (size_t)b * DD * SS + s;

    for (int idx = t; idx < 256 * 52; idx += 256) {
        int d = idx / 52, k = idx - d * 52;
        tvs[idx] = (k < KK) ? g_tvn[d * KK + k] : 0.0f;
    }
    for (int i = t; i < KK * 128; i += 256) hloc[i] = 0;
    __syncthreads();

    unsigned long long acc2[26];
    #pragma unroll
    for (int p = 0; p < 26; p++) acc2[p] = 0ull;
    float ssq = 0.f;

    float xbuf[4];
    #pragma unroll
    for (int i = 0; i < 4; i++) xbuf[i] = fb[(size_t)i * SS];

    for (int d0 = 0; d0 < 256; d0 += 4) {
        float xn[4];
        if (d0 < 252) {
            #pragma unroll
            for (int i = 0; i < 4; i++) xn[i] = fb[(size_t)(d0 + 4 + i) * SS];
        }
        #pragma unroll
        for (int i = 0; i < 4; i++) {
            int d = d0 + i;
            unsigned long long x2 = dup2(xbuf[i]);
            const ulonglong2* tp = (const ulonglong2*)(tvs + d * 52);
            #pragma unroll
            for (int p = 0; p < 13; p++) {
                ulonglong2 w = tp[p];
                acc2[2 * p]     = fma2(x2, w.x, acc2[2 * p]);
                acc2[2 * p + 1] = fma2(x2, w.y, acc2[2 * p + 1]);
            }
            ssq = fmaf(xbuf[i], xbuf[i], ssq);
        }
        #pragma unroll
        for (int i = 0; i < 4; i++) xbuf[i] = xn[i];
    }

    // epilogue (fully per-thread; no cross-thread reductions)
    float r = 1.0f / fmaxf(sqrtf(ssq), 1e-12f);
    g_rnorm[gRow] = r;

    float msk[50];
    float sum = 0.f;
    #pragma unroll
    for (int p = 0; p < 25; p++) {
        float t0, t1;
        unpk(acc2[p], t0, t1);
        int k0 = 2 * p, k1 = 2 * p + 1;
        float tpn0 = t0 * r, tpn1 = t1 * r;
        g_tpnT[(size_t)k0 * NROW + gRow] = tpn0;   // coalesced across warp
        g_tpnT[(size_t)k1 * NROW + gRow] = tpn1;
        int b0 = (int)(tpn0 * 128.0f);
        if (b0 >= 8) atomicAdd(&hloc[k0 * 128 + min(b0, 127)], 1);
        int b1 = (int)(tpn1 * 128.0f);
        if (b1 >= 8) atomicAdd(&hloc[k1 * 128 + min(b1, 127)], 1);
        float m0 = (tpn0 > 0.3f) ? t0 : 0.0f;
        float m1 = (tpn1 > 0.3f) ? t1 : 0.0f;
        msk[k0] = m0; msk[k1] = m1;
        sum += m0; sum += m1;
    }
    float inv = 1.0f / (sum + 0.001f + 1e-8f);
    // OUT_TPNN is an odd offset: out+259 is only 4B-aligned -> SCALAR stores.
    float* tpnn = out + OUT_TPNN + (size_t)gRow * KK;
    #pragma unroll
    for (int k = 0; k < 50; k++) {
        tpnn[k] = msk[k] * inv;
    }
    __syncthreads();
    for (int i = t; i < KK * 128; i += 256) {
        int c = hloc[i];
        if (c) atomicAdd(&g_hist[i], c);
    }
}

// ============ A2: rec1 GEMM (f32x2) + bf16 store + fp32 colsums =========
// grid 4096 (16-row tiles), 256 threads = (j in 16) x (hc in 16)
#define SH_STR 260
#define A2_SMEM ((KK * HH + 16 * 52) * 4 > (16 * SH_STR) * 4 ? (KK * HH + 16 * 52) * 4 : (16 * SH_STR) * 4)

__global__ void __launch_bounds__(256, 4) kernelA2(const float* __restrict__ tpnn,
                                                   const float* __restrict__ rec1) {
    extern __shared__ float sm2[];
    float* srec = sm2;                   // [50][256] natural
    float* snn  = sm2 + KK * HH;         // [16][52]

    int t = threadIdx.x;
    int j = t >> 4, hc = t & 15;
    int row0 = blockIdx.x * 16;
    int row = row0 + j;

    for (int idx = t; idx < KK * HH; idx += 256) srec[idx] = rec1[idx];
    for (int idx = t; idx < 16 * KK; idx += 256) {
        int rr = idx / KK, k = idx - rr * KK;
        snn[rr * 52 + k] = tpnn[(size_t)(row0 + rr) * KK + k];
    }
    __syncthreads();

    unsigned long long acc2[8];
    #pragma unroll
    for (int p = 0; p < 8; p++) acc2[p] = 0ull;

    #pragma unroll 2
    for (int k = 0; k < KK; k++) {
        unsigned long long n2 = dup2(snn[j * 52 + k]);
        const float* wr = srec + k * HH + hc * 2;
        #pragma unroll
        for (int p = 0; p < 8; p++) {
            unsigned long long w = *(const unsigned long long*)(wr + 32 * p);
            acc2[p] = fma2(n2, w, acc2[p]);
        }
    }
    __syncthreads();                     // done reading srec/snn; reuse as sh
    float* sh = sm2;                     // [16][SH_STR]
    #pragma unroll
    for (int p = 0; p < 8; p++) {
        float v0, v1;
        unpk(acc2[p], v0, v1);
        v0 = fmaxf(v0, 0.f);
        v1 = fmaxf(v1, 0.f);
        int h = hc * 2 + 32 * p;
        __nv_bfloat162 bb = __floats2bfloat162_rn(v0, v1);
        *(uint32_t*)&g_rec1o_bf[(size_t)row * HH + h] = *(uint32_t*)&bb;
        sh[j * SH_STR + h] = v0;
        sh[j * SH_STR + h + 1] = v1;
    }
    __syncthreads();
    {
        float s = 0.f;
        #pragma unroll
        for (int j2 = 0; j2 < 16; j2++) s += sh[j2 * SH_STR + t];
        g_hpart[(size_t)blockIdx.x * HH + t] = s;
    }
}

// ============ predK: rowrec[b][d] = (sum_s rec1out) @ rec2 (fp32) ========
__global__ void __launch_bounds__(256) predK(const float* __restrict__ rec2) {
    __shared__ float hs[HH];
    int b = blockIdx.x, d = threadIdx.x;
    float s = 0.f;
    for (int i = 0; i < 32; i++) s += g_hpart[(size_t)(b * 32 + i) * HH + d];
    hs[d] = s;
    __syncthreads();
    float acc = 0.f;
    #pragma unroll 8
    for (int h = 0; h < HH; h++) acc += hs[h] * rec2[h * DD + d];
    g_rowrec[b * DD + d] = acc;
}

// =================== kernelB: bf16 tensor-core GEMM + fused ae ==========
__device__ __forceinline__ void mma_bf16(float* c, uint32_t a0, uint32_t a1,
                                         uint32_t a2, uint32_t a3,
                                         uint32_t b0, uint32_t b1) {
    asm volatile(
        "mma.sync.aligned.m16n8k16.row.col.f32.bf16.bf16.f32 "
        "{%0,%1,%2,%3},{%4,%5,%6,%7},{%8,%9},{%0,%1,%2,%3};"
        : "+f"(c[0]), "+f"(c[1]), "+f"(c[2]), "+f"(c[3])
        : "r"(a0), "r"(a1), "r"(a2), "r"(a3), "r"(b0), "r"(b1));
}

__global__ void __launch_bounds__(256) kernelB(const float* __restrict__ fin) {
    __shared__ float rns[128];
    __shared__ float aew[8];

    int t = threadIdx.x;
    int warp = t >> 5, lane = t & 31;
    int g = lane >> 2, tid = lane & 3;
    int wm = warp >> 2, wn = warp & 3;
    int mt = blockIdx.y, nt_blk = blockIdx.x;
    int row0 = mt * 128;
    int n0 = nt_blk * 128;
    int b = row0 >> 9;
    int sbase = row0 & 511;

    if (t < 128) rns[t] = g_rnorm[row0 + t];

    float acc[4][4][4] = {};

    const __nv_bfloat16* Abase = g_rec1o_bf + (size_t)(row0 + wm * 64) * HH;
    const __nv_bfloat16* Bbase = g_rec2T_bf + (size_t)(n0 + wn * 32) * HH;

    #pragma unroll 1
    for (int k0 = 0; k0 < HH; k0 += 16) {
        uint32_t bf[4][2];
        #pragma unroll
        for (int nt = 0; nt < 4; nt++) {
            const __nv_bfloat16* bp = Bbase + (nt * 8 + g) * HH + k0 + tid * 2;
            bf[nt][0] = *(const uint32_t*)bp;
            bf[nt][1] = *(const uint32_t*)(bp + 8);
        }
        #pragma unroll
        for (int mtile = 0; mtile < 4; mtile++) {
            const __nv_bfloat16* ap = Abase + (mtile * 16 + g) * HH + k0 + tid * 2;
            uint32_t a0 = *(const uint32_t*)ap;
            uint32_t a1 = *(const uint32_t*)(ap + 8 * HH);
            uint32_t a2 = *(const uint32_t*)(ap + 8);
            uint32_t a3 = *(const uint32_t*)(ap + 8 * HH + 8);
            #pragma unroll
            for (int nt = 0; nt < 4; nt++)
                mma_bf16(acc[mtile][nt], a0, a1, a2, a3, bf[nt][0], bf[nt][1]);
        }
    }

    float aeacc = 0.f;
    const float* fbase = fin + (size_t)b * DD * SS;
    #pragma unroll
    for (int mtile = 0; mtile < 4; mtile++) {
        #pragma unroll
        for (int half = 0; half < 2; half++) {
            int r = wm * 64 + mtile * 16 + g + half * 8;
            float rnv = rns[r];
            int s = sbase + r;
            #pragma unroll
            for (int nt = 0; nt < 4; nt++) {
                #pragma unroll
                for (int c = 0; c < 2; c++) {
                    int d = n0 + wn * 32 + nt * 8 + tid * 2 + c;
                    float o = acc[mtile][nt][half * 2 + c];
                    float xn = fbase[(size_t)d * SS + s] * rnv;
                    float df = xn - o;
                    aeacc += df * df;
                }
            }
        }
    }
    #pragma unroll
    for (int off = 16; off >= 1; off >>= 1)
        aeacc += __shfl_xor_sync(0xffffffffu, aeacc, off);
    if (lane == 0) aew[warp] = aeacc;
    __syncthreads();
    if (t == 0) {
        float s = 0.f;
        #pragma unroll
        for (int w = 0; w < 8; w++) s += aew[w];
        g_aepart[mt * 2 + nt_blk] = s;
    }
}

// =========== top-k chain: threshold -> collect -> select ================
__global__ void threshK() {
    int k = blockIdx.x;
    int lane = threadIdx.x;
    int cum = 0, bstar = 7;
    for (int base = 127; base >= 8 && bstar == 7; base -= 32) {
        int bb = base - lane;
        int cnt = (bb >= 8) ? g_hist[k * 128 + bb] : 0;
        int incl = cnt;
        #pragma unroll
        for (int off = 1; off < 32; off <<= 1) {
            int v = __shfl_up_sync(0xffffffffu, incl, off);
            if (lane >= off) incl += v;
        }
        int total = __shfl_sync(0xffffffffu, incl, 31);
        unsigned mask = __ballot_sync(0xffffffffu, (cum + incl >= 32) && bb >= 8);
        if (mask) bstar = base - (__ffs(mask) - 1);
        cum += total;
    }
    if (lane == 0) g_bstar[k] = bstar;
}

__global__ void __launch_bounds__(256) collectK() {
    int t = threadIdx.x;
    int row0 = blockIdx.x * 256;
    #pragma unroll 2
    for (int k = 0; k < KK; k++) {
        float v = g_tpnT[(size_t)k * NROW + row0 + t];
        int bin = (int)(v * 128.0f);
        int bs = g_bstar[k];
        if (bin >= bs || bs == 7) {
            int idx = atomicAdd(&g_candcnt[k], 1);
            g_cand[(size_t)k * NROW + idx] = v;
        }
    }
}

__global__ void __launch_bounds__(256) finalC() {
    int k = blockIdx.x, t = threadIdx.x;
    int C = g_candcnt[k];
    __shared__ float vals[8192];
    __shared__ float rmax[256];
    __shared__ int   rarg[256];
    float* v;
    if (C <= 8192) {
        for (int i = t; i < C; i += 256) vals[i] = g_cand[(size_t)k * NROW + i];
        v = vals;
    } else {
        v = &g_cand[(size_t)k * NROW];
    }
    __syncthreads();
    float sum = 0.f;
    int rounds = C < 32 ? C : 32;
    for (int r = 0; r < rounds; r++) {
        float m = -1e30f; int mi = -1;
        for (int i = t; i < C; i += 256) {
            float x = v[i];
            if (x > m) { m = x; mi = i; }
        }
        rmax[t] = m; rarg[t] = mi;
        __syncthreads();
        for (int off = 128; off > 0; off >>= 1) {
            if (t < off && rmax[t + off] > rmax[t]) { rmax[t] = rmax[t + off]; rarg[t] = rarg[t + off]; }
            __syncthreads();
        }
        if (t == 0) { sum += rmax[0]; v[rarg[0]] = -1e30f; }
        __syncthreads();
    }
    if (t == 0) g_topsum[k] = sum;
}

// =================== final: reductions + pred head =======================
__global__ void __launch_bounds__(256) finalK(const float* __restrict__ Wc,
                                              const float* __restrict__ bc,
                                              float* __restrict__ out) {
    __shared__ float red[256];
    int t = threadIdx.x;
    float s = 0.f;
    for (int i = t; i < 1024; i += 256) s += g_aepart[i];
    red[t] = s;
    __syncthreads();
    for (int off = 128; off > 0; off >>= 1) {
        if (t < off) red[t] += red[t + off];
        __syncthreads();
    }
    if (t == 0) {
        out[OUT_AE] = red[0] / 16777216.0f;
        float cs = 0.f;
        for (int k = 0; k < KK; k++) cs += g_topsum[k];
        out[OUT_CSIM] = -cs / 1600.0f;
    }
    {
        int bi = t >> 1, c = t & 1;
        float acc = 0.f;
        for (int d = 0; d < DD; d++)
            acc += g_rowrec[bi * DD + d] * Wc[d * 2 + c];
        out[bi * 2 + c] = acc * (1.0f / 512.0f) + bc[c];
    }
}

// ============================ launcher ===================================
extern "C" void kernel_launch(void* const* d_in, const int* in_sizes, int n_in,
                              void* d_out, int out_size) {
    const float* f_input      = (const float*)d_in[0];
    const float* topic_vector = (const float*)d_in[2];
    const float* rec1         = (const float*)d_in[3];
    const float* rec2         = (const float*)d_in[4];
    const float* Wc           = (const float*)d_in[5];
    const float* bc           = (const float*)d_in[6];
    float* out = (float*)d_out;

    cudaFuncSetAttribute(kernelA1, cudaFuncAttributeMaxDynamicSharedMemorySize, A1_SMEM);
    cudaFuncSetAttribute(kernelA2, cudaFuncAttributeMaxDynamicSharedMemorySize, A2_SMEM);

    prep2<<<257, 256>>>(topic_vector, rec2, out);
    kernelA1<<<256, 256, A1_SMEM>>>(f_input, out);
    kernelA2<<<4096, 256, A2_SMEM>>>((const float*)(out + OUT_TPNN), rec1);
    kernelB<<<dim3(2, 512), 256>>>(f_input);   // launch index 3 -> profiled
    threshK<<<KK, 32>>>();
    collectK<<<256, 256>>>();
    finalC<<<KK, 256>>>();
    predK<<<BB, 256>>>(rec2);
    finalK<<<1, 256>>>(Wc, bc, out);
}

// round 7
// speedup vs baseline: 1.6772x; 1.6772x over previous
#include <cuda_runtime.h>
#include <cuda_bf16.h>
#include <math.h>
#include <stdint.h>

// Problem constants
#define BB   128
#define DD   256
#define SS   512
#define KK   50
#define HH   256
#define NROW 65536           // B*S
#define OUT_PRED   0         // 256 floats
#define OUT_ZERO   256
#define OUT_CSIM   257
#define OUT_CFAR   258
#define OUT_TPNN   259       // 3,276,800 floats (ODD offset: scalar stores only!)
#define OUT_AE     3277059

// -------- scratch (static device memory; no allocations allowed) --------
__device__ float g_tvn[DD * KK];                   // normalized topic vectors [d][k]
__device__ float g_rnorm[NROW];                    // 1/max(||x||,1e-12) per row
__device__ float g_tpnT[(size_t)KK * NROW];        // topic_prob_n transposed [k][row]
__device__ __nv_bfloat16 g_rec1o_bf[(size_t)NROW * HH]; // relu(nn@rec1) bf16
__device__ __nv_bfloat16 g_rec2T_bf[DD * HH];      // rec2 transposed [d][h] bf16
__device__ float g_hpart[512 * HH];                // per-kernelA-CTA fp32 colsums
__device__ float g_rowrec[BB * DD];                // fp32 (sum_s rec1out) @ rec2
__device__ float g_aepart[1024];                   // per-kernelB-CTA ae partials
__device__ float g_topsum[KK];                     // per-concept top-32 sums
// top-k selection scratch
__device__ int   g_hist[KK * 128];
__device__ int   g_bstar[KK];
__device__ int   g_candcnt[KK];
__device__ float g_cand[(size_t)KK * NROW];

// =========== prep2: tv_n + concept_far + zero scratch + rec2 bf16 T =====
__global__ void prep2(const float* __restrict__ tv, const float* __restrict__ rec2,
                      float* __restrict__ out) {
    int t = threadIdx.x;                 // 256 threads
    if (blockIdx.x > 0) {                // convT part: blocks 1..256 -> d
        int d = blockIdx.x - 1;
        g_rec2T_bf[d * HH + t] = __float2bfloat16(rec2[t * DD + d]);
        return;
    }
    __shared__ float cinv[64];
    __shared__ float sd[DD];
    for (int i = t; i < KK * 128; i += 256) g_hist[i] = 0;
    if (t < KK) g_candcnt[t] = 0;
    if (t < KK) {
        float s = 0.f;
        for (int d = 0; d < DD; d++) { float v = tv[d * KK + t]; s += v * v; }
        cinv[t] = 1.0f / fmaxf(sqrtf(s), 1e-12f);
    }
    __syncthreads();
    {   // thread t == d
        float sum = 0.f;
        for (int k = 0; k < KK; k++) {
            float v = tv[t * KK + k] * cinv[k];
            g_tvn[t * KK + k] = v;
            sum += v;
        }
        sd[t] = sum;
    }
    __syncthreads();
    if (t == 0) {
        float g = 0.f;
        for (int d = 0; d < DD; d++) g += sd[d] * sd[d];
        out[OUT_CFAR] = (g - (float)KK) / (float)(KK * KK);
        out[OUT_ZERO] = 0.0f;
    }
}

// =================== kernelA: topic path + rec1 (round-4 proven) ========
#define XS_F  (256 * 128)
#define TVS_F (256 * 52)
#define TPS_F (128 * 52)
#define SMEM_A_BYTES ((XS_F + TVS_F + TPS_F + 128 + 512) * 4)

__global__ void __launch_bounds__(512) kernelA(const float* __restrict__ fin,
                                               const float* __restrict__ rec1,
                                               float* __restrict__ out) {
    extern __shared__ float sm[];
    float* xs  = sm;                   // [256 d][128 j]
    float* tvs = xs + XS_F;            // [256 d][52 k] (later rec1 [50][256])
    float* tps = tvs + TVS_F;          // [128 j][52 k] (later colsum scratch)
    float* rn  = tps + TPS_F;          // [128]
    float* ps  = rn + 128;             // [128][4]

    int t = threadIdx.x;
    int cid = blockIdx.x;
    int b = cid >> 2, st = cid & 3;
    int s0 = st * 128;
    int row0 = b * SS + s0;
    const float* fb = fin + (size_t)b * DD * SS + s0;

    #pragma unroll 4
    for (int it = 0; it < 64; it++) {
        int idx = t + 512 * it;
        int d = idx >> 7, j = idx & 127;
        xs[d * 128 + j] = fb[(size_t)d * SS + j];
    }
    for (int idx = t; idx < TVS_F; idx += 512) {
        int d = idx / 52, k = idx - d * 52;
        tvs[idx] = (k < KK) ? g_tvn[d * KK + k] : 0.0f;
    }
    __syncthreads();

    {
        int j = t >> 2, q = t & 3;
        const float* xp = xs + (q * 64) * 128 + j;
        float s = 0.f;
        #pragma unroll 8
        for (int d = 0; d < 64; d++) { float v = xp[d * 128]; s += v * v; }
        ps[j * 4 + q] = s;
    }
    __syncthreads();
    if (t < 128) {
        float s = ps[t * 4] + ps[t * 4 + 1] + ps[t * 4 + 2] + ps[t * 4 + 3];
        float r = 1.0f / fmaxf(sqrtf(s), 1e-12f);
        rn[t] = r;
        g_rnorm[row0 + t] = r;
    }
    __syncthreads();

    if (t < 416) {
        int jt = t / 13, kt = t - jt * 13;
        const float* xb = xs + jt * 4;
        const float* tb = tvs + kt * 4;
        float acc[4][4] = {};
        #pragma unroll 4
        for (int d = 0; d < DD; d++) {
            float4 xv = *(const float4*)(xb + d * 128);
            float4 tw = *(const float4*)(tb + d * 52);
            float xr[4] = {xv.x, xv.y, xv.z, xv.w};
            float tr[4] = {tw.x, tw.y, tw.z, tw.w};
            #pragma unroll
            for (int r = 0; r < 4; r++)
                #pragma unroll
                for (int c = 0; c < 4; c++)
                    acc[r][c] += xr[r] * tr[c];
        }
        #pragma unroll
        for (int r = 0; r < 4; r++)
            #pragma unroll
            for (int c = 0; c < 4; c++)
                tps[(jt * 4 + r) * 52 + kt * 4 + c] = acc[r][c];
    }
    __syncthreads();

    int j = t >> 2, q = t & 3;
    int gRow = row0 + j;
    {
        float partial = 0.f;
        float rj = rn[j];
        #pragma unroll
        for (int i = 0; i < 13; i++) {
            int k = q + 4 * i;
            if (k < KK) {
                float tp = tps[j * 52 + k];
                float tpn = tp * rj;
                g_tpnT[(size_t)k * NROW + gRow] = tpn;
                float m = (tpn > 0.3f) ? tp : 0.0f;
                tps[j * 52 + k] = m;
                partial += m;
            }
        }
        ps[j * 4 + q] = partial;
    }
    __syncthreads();
    if (t < 128) {
        float s = ps[t * 4] + ps[t * 4 + 1] + ps[t * 4 + 2] + ps[t * 4 + 3];
        rn[t] = 1.0f / (s + 0.001f + 1e-8f);
    }
    __syncthreads();
    {
        float inv = rn[j];
        float* tpnn = out + OUT_TPNN;
        #pragma unroll
        for (int i = 0; i < 13; i++) {
            int k = q + 4 * i;
            if (k < KK) {
                float nv = tps[j * 52 + k] * inv;
                tps[j * 52 + k] = nv;
                tpnn[(size_t)gRow * KK + k] = nv;
            }
        }
    }
    __syncthreads();

    for (int idx = t; idx < KK * HH; idx += 512) tvs[idx] = rec1[idx];
    __syncthreads();

    // rec1out = relu(nn @ rec1): bf16 store + fp32 column-sum partials.
    float colp[4] = {};
    #pragma unroll
    for (int it = 0; it < 4; it++) {
        int idx = t + 512 * it;
        int jt = idx >> 6, ht = idx & 63;
        int j0 = jt * 4, h0 = ht * 4;
        float acc[4][4] = {};
        #pragma unroll 2
        for (int k = 0; k < KK; k++) {
            float nv[4];
            #pragma unroll
            for (int r = 0; r < 4; r++) nv[r] = tps[(j0 + r) * 52 + k];
            float4 rv = *(const float4*)(tvs + k * HH + h0);
            float rr[4] = {rv.x, rv.y, rv.z, rv.w};
            #pragma unroll
            for (int r = 0; r < 4; r++)
                #pragma unroll
                for (int c = 0; c < 4; c++)
                    acc[r][c] += nv[r] * rr[c];
        }
        #pragma unroll
        for (int r = 0; r < 4; r++) {
            float v0 = fmaxf(acc[r][0], 0.f), v1 = fmaxf(acc[r][1], 0.f);
            float v2 = fmaxf(acc[r][2], 0.f), v3 = fmaxf(acc[r][3], 0.f);
            colp[0] += v0; colp[1] += v1; colp[2] += v2; colp[3] += v3;
            __nv_bfloat162 p0 = __floats2bfloat162_rn(v0, v1);
            __nv_bfloat162 p1 = __floats2bfloat162_rn(v2, v3);
            uint2 pk;
            pk.x = *(uint32_t*)&p0;
            pk.y = *(uint32_t*)&p1;
            *(uint2*)(g_rec1o_bf + (size_t)(row0 + j0 + r) * HH + h0) = pk;
        }
    }
    __syncthreads();          // all reads of tps done; reuse as colsum scratch
    {
        float* ps2 = tps;     // [256 h][8 q]
        int ht = t & 63, qq = t >> 6;
        #pragma unroll
        for (int c = 0; c < 4; c++) ps2[(ht * 4 + c) * 8 + qq] = colp[c];
        __syncthreads();
        if (t < 256) {
            float s = 0.f;
            #pragma unroll
            for (int q2 = 0; q2 < 8; q2++) s += ps2[t * 8 + q2];
            g_hpart[cid * HH + t] = s;
        }
    }
}

// ============ predK: rowrec[b][d] = (sum_s rec1out) @ rec2 (fp32) ========
__global__ void __launch_bounds__(256) predK(const float* __restrict__ rec2) {
    __shared__ float hs[HH];
    int b = blockIdx.x, d = threadIdx.x;
    hs[d] = g_hpart[(b * 4 + 0) * HH + d] + g_hpart[(b * 4 + 1) * HH + d]
          + g_hpart[(b * 4 + 2) * HH + d] + g_hpart[(b * 4 + 3) * HH + d];
    __syncthreads();
    float acc = 0.f;
    #pragma unroll 8
    for (int h = 0; h < HH; h++) acc += hs[h] * rec2[h * DD + d];
    g_rowrec[b * DD + d] = acc;
}

// ====== kernelB: smem-staged bf16 mma (ldmatrix) + fused ae =============
// CTA tile 128x128, 8 warps: wm in {0,1} x wn in {0..3}; warp tile 64x32.
// Tiles staged whole: A[128][264] bf16, B[128][264] bf16 (528B rows:
// row offsets mod 32 banks cycle 0,4,8,...,28 -> LDSM conflict-free).
#define TSTR 264
#define B_SMEM_BYTES (2 * 128 * TSTR * 2)

__device__ __forceinline__ void mma_bf16(float* c, uint32_t a0, uint32_t a1,
                                         uint32_t a2, uint32_t a3,
                                         uint32_t b0, uint32_t b1) {
    asm volatile(
        "mma.sync.aligned.m16n8k16.row.col.f32.bf16.bf16.f32 "
        "{%0,%1,%2,%3},{%4,%5,%6,%7},{%8,%9},{%0,%1,%2,%3};"
        : "+f"(c[0]), "+f"(c[1]), "+f"(c[2]), "+f"(c[3])
        : "r"(a0), "r"(a1), "r"(a2), "r"(a3), "r"(b0), "r"(b1));
}
__device__ __forceinline__ void ldsm_x4(uint32_t& r0, uint32_t& r1,
                                        uint32_t& r2, uint32_t& r3, uint32_t addr) {
    asm volatile("ldmatrix.sync.aligned.m8n8.x4.shared.b16 {%0,%1,%2,%3}, [%4];"
                 : "=r"(r0), "=r"(r1), "=r"(r2), "=r"(r3) : "r"(addr));
}
__device__ __forceinline__ void ldsm_x2(uint32_t& r0, uint32_t& r1, uint32_t addr) {
    asm volatile("ldmatrix.sync.aligned.m8n8.x2.shared.b16 {%0,%1}, [%2];"
                 : "=r"(r0), "=r"(r1) : "r"(addr));
}

__global__ void __launch_bounds__(256) kernelB(const float* __restrict__ fin) {
    extern __shared__ __nv_bfloat16 smB[];
    __nv_bfloat16* As = smB;                 // [128][TSTR]
    __nv_bfloat16* Bs = smB + 128 * TSTR;    // [128][TSTR]
    __shared__ float rns[128];
    __shared__ float aew[8];

    int t = threadIdx.x;
    int warp = t >> 5, lane = t & 31;
    int g = lane >> 2, tid = lane & 3;
    int wm = warp >> 2, wn = warp & 3;
    int mt = blockIdx.y, nt_blk = blockIdx.x;
    int row0 = mt * 128;
    int n0 = nt_blk * 128;
    int b = row0 >> 9;
    int sbase = row0 & 511;

    if (t < 128) rns[t] = g_rnorm[row0 + t];

    // stage tiles: each warp loads one full 512B row per pass (coalesced)
    {
        const __nv_bfloat16* Agm = g_rec1o_bf + (size_t)row0 * HH;
        const __nv_bfloat16* Bgm = g_rec2T_bf + (size_t)n0 * HH;
        int r = t >> 5, c = t & 31;          // row within octet, 16B chunk
        #pragma unroll
        for (int i = 0; i < 16; i++) {
            int row = r + 8 * i;
            *(float4*)(As + row * TSTR + c * 8) = *(const float4*)(Agm + (size_t)row * HH + c * 8);
            *(float4*)(Bs + row * TSTR + c * 8) = *(const float4*)(Bgm + (size_t)row * HH + c * 8);
        }
    }
    __syncthreads();

    float acc[4][4][4] = {};

    const __nv_bfloat16* Awarp = As + (wm * 64 + (lane & 15)) * TSTR + (lane >> 4) * 8;
    const __nv_bfloat16* Bwarp = Bs + (wn * 32 + (lane & 7)) * TSTR + ((lane >> 3) & 1) * 8;
    uint32_t aBase = (uint32_t)__cvta_generic_to_shared(Awarp);
    uint32_t bBase = (uint32_t)__cvta_generic_to_shared(Bwarp);

    #pragma unroll 2
    for (int k0 = 0; k0 < HH; k0 += 16) {
        uint32_t bfr[4][2];
        #pragma unroll
        for (int nt = 0; nt < 4; nt++)
            ldsm_x2(bfr[nt][0], bfr[nt][1], bBase + (nt * 8 * TSTR + k0) * 2);
        #pragma unroll
        for (int mtile = 0; mtile < 4; mtile++) {
            uint32_t a0, a1, a2, a3;
            ldsm_x4(a0, a1, a2, a3, aBase + (mtile * 16 * TSTR + k0) * 2);
            #pragma unroll
            for (int nt = 0; nt < 4; nt++)
                mma_bf16(acc[mtile][nt], a0, a1, a2, a3, bfr[nt][0], bfr[nt][1]);
        }
    }

    // ---- epilogue: ae partials ----
    float aeacc = 0.f;
    const float* fbase = fin + (size_t)b * DD * SS;
    #pragma unroll
    for (int mtile = 0; mtile < 4; mtile++) {
        #pragma unroll
        for (int half = 0; half < 2; half++) {
            int r = wm * 64 + mtile * 16 + g + half * 8;
            float rnv = rns[r];
            int s = sbase + r;
            #pragma unroll
            for (int nt = 0; nt < 4; nt++) {
                #pragma unroll
                for (int c = 0; c < 2; c++) {
                    int d = n0 + wn * 32 + nt * 8 + tid * 2 + c;
                    float o = acc[mtile][nt][half * 2 + c];
                    float xn = fbase[(size_t)d * SS + s] * rnv;
                    float df = xn - o;
                    aeacc += df * df;
                }
            }
        }
    }
    #pragma unroll
    for (int off = 16; off >= 1; off >>= 1)
        aeacc += __shfl_xor_sync(0xffffffffu, aeacc, off);
    if (lane == 0) aew[warp] = aeacc;
    __syncthreads();
    if (t == 0) {
        float s = 0.f;
        #pragma unroll
        for (int w = 0; w < 8; w++) s += aew[w];
        g_aepart[mt * 2 + nt_blk] = s;
    }
}

// =========== top-k chain: histogram -> threshold -> collect -> select ====
__global__ void __launch_bounds__(256) histK() {
    __shared__ int h[KK * 128];
    int t = threadIdx.x;
    int row0 = blockIdx.x * 256;
    for (int i = t; i < KK * 128; i += 256) h[i] = 0;
    __syncthreads();
    #pragma unroll 2
    for (int k = 0; k < KK; k++) {
        float v = g_tpnT[(size_t)k * NROW + row0 + t];
        int bin = (int)(v * 128.0f);
        if (bin >= 8) atomicAdd(&h[k * 128 + min(bin, 127)], 1);
    }
    __syncthreads();
    for (int i = t; i < KK * 128; i += 256) {
        int c = h[i];
        if (c) atomicAdd(&g_hist[i], c);
    }
}

__global__ void threshK() {
    int k = blockIdx.x;
    int lane = threadIdx.x;
    int cum = 0, bstar = 7;
    for (int base = 127; base >= 8 && bstar == 7; base -= 32) {
        int bb = base - lane;
        int cnt = (bb >= 8) ? g_hist[k * 128 + bb] : 0;
        int incl = cnt;
        #pragma unroll
        for (int off = 1; off < 32; off <<= 1) {
            int v = __shfl_up_sync(0xffffffffu, incl, off);
            if (lane >= off) incl += v;
        }
        int total = __shfl_sync(0xffffffffu, incl, 31);
        unsigned mask = __ballot_sync(0xffffffffu, (cum + incl >= 32) && bb >= 8);
        if (mask) bstar = base - (__ffs(mask) - 1);
        cum += total;
    }
    if (lane == 0) g_bstar[k] = bstar;
}

__global__ void __launch_bounds__(256) collectK() {
    int t = threadIdx.x;
    int row0 = blockIdx.x * 256;
    #pragma unroll 2
    for (int k = 0; k < KK; k++) {
        float v = g_tpnT[(size_t)k * NROW + row0 + t];
        int bin = (int)(v * 128.0f);
        int bs = g_bstar[k];
        if (bin >= bs || bs == 7) {
            int idx = atomicAdd(&g_candcnt[k], 1);
            g_cand[(size_t)k * NROW + idx] = v;
        }
    }
}

__global__ void __launch_bounds__(256) finalC() {
    int k = blockIdx.x, t = threadIdx.x;
    int C = g_candcnt[k];
    __shared__ float vals[8192];
    __shared__ float rmax[256];
    __shared__ int   rarg[256];
    float* v;
    if (C <= 8192) {
        for (int i = t; i < C; i += 256) vals[i] = g_cand[(size_t)k * NROW + i];
        v = vals;
    } else {
        v = &g_cand[(size_t)k * NROW];
    }
    __syncthreads();
    float sum = 0.f;
    int rounds = C < 32 ? C : 32;
    for (int r = 0; r < rounds; r++) {
        float m = -1e30f; int mi = -1;
        for (int i = t; i < C; i += 256) {
            float x = v[i];
            if (x > m) { m = x; mi = i; }
        }
        rmax[t] = m; rarg[t] = mi;
        __syncthreads();
        for (int off = 128; off > 0; off >>= 1) {
            if (t < off && rmax[t + off] > rmax[t]) { rmax[t] = rmax[t + off]; rarg[t] = rarg[t + off]; }
            __syncthreads();
        }
        if (t == 0) { sum += rmax[0]; v[rarg[0]] = -1e30f; }
        __syncthreads();
    }
    if (t == 0) g_topsum[k] = sum;
}

// =================== final: reductions + pred head =======================
__global__ void __launch_bounds__(256) finalK(const float* __restrict__ Wc,
                                              const float* __restrict__ bc,
                                              float* __restrict__ out) {
    __shared__ float red[256];
    int t = threadIdx.x;
    float s = 0.f;
    for (int i = t; i < 1024; i += 256) s += g_aepart[i];
    red[t] = s;
    __syncthreads();
    for (int off = 128; off > 0; off >>= 1) {
        if (t < off) red[t] += red[t + off];
        __syncthreads();
    }
    if (t == 0) {
        out[OUT_AE] = red[0] / 16777216.0f;
        float cs = 0.f;
        for (int k = 0; k < KK; k++) cs += g_topsum[k];
        out[OUT_CSIM] = -cs / 1600.0f;
    }
    {
        int bi = t >> 1, c = t & 1;
        float acc = 0.f;
        for (int d = 0; d < DD; d++)
            acc += g_rowrec[bi * DD + d] * Wc[d * 2 + c];
        out[bi * 2 + c] = acc * (1.0f / 512.0f) + bc[c];
    }
}

// ============================ launcher ===================================
extern "C" void kernel_launch(void* const* d_in, const int* in_sizes, int n_in,
                              void* d_out, int out_size) {
    const float* f_input      = (const float*)d_in[0];
    const float* topic_vector = (const float*)d_in[2];
    const float* rec1         = (const float*)d_in[3];
    const float* rec2         = (const float*)d_in[4];
    const float* Wc           = (const float*)d_in[5];
    const float* bc           = (const float*)d_in[6];
    float* out = (float*)d_out;

    cudaFuncSetAttribute(kernelA, cudaFuncAttributeMaxDynamicSharedMemorySize, SMEM_A_BYTES);
    cudaFuncSetAttribute(kernelB, cudaFuncAttributeMaxDynamicSharedMemorySize, B_SMEM_BYTES);

    prep2<<<257, 256>>>(topic_vector, rec2, out);          // idx 0
    kernelA<<<512, 512, SMEM_A_BYTES>>>(f_input, rec1, out); // idx 1
    histK<<<256, 256>>>();                                 // idx 2
    kernelB<<<dim3(2, 512), 256, B_SMEM_BYTES>>>(f_input); // idx 3 -> profiled
    threshK<<<KK, 32>>>();
    collectK<<<256, 256>>>();
    finalC<<<KK, 256>>>();
    predK<<<BB, 256>>>(rec2);
    finalK<<<1, 256>>>(Wc, bc, out);
}

// round 8
// speedup vs baseline: 2.4659x; 1.4702x over previous
#include <cuda_runtime.h>
#include <cuda_bf16.h>
#include <math.h>
#include <stdint.h>

// Problem constants
#define BB   128
#define DD   256
#define SS   512
#define KK   50
#define HH   256
#define NROW 65536           // B*S
#define OUT_PRED   0         // 256 floats
#define OUT_ZERO   256
#define OUT_CSIM   257
#define OUT_CFAR   258
#define OUT_TPNN   259       // 3,276,800 floats (ODD offset: scalar stores only!)
#define OUT_AE     3277059

// -------- scratch (static device memory; no allocations allowed) --------
__device__ float g_tvn[DD * KK];                 // normalized topic vectors [d][k]
__device__ float g_rnorm[NROW];                  // 1/max(||x||,1e-12) per row
__device__ float g_tpnT[(size_t)KK * NROW];      // topic_prob_n transposed [k][row]
__device__ float g_aepartA[512];                 // per-kernelA-CTA sum of ||xn||^2
__device__ float g_corr[NROW];                   // per-row ae correction (sparse)
__device__ float g_hsum[BB * HH];                // sum_s relu(nn@rec1) per batch (fp32)
__device__ float g_rowrec[BB * DD];              // hsum @ rec2
__device__ float g_topsum[KK];                   // per-concept top-32 sums
__device__ int   g_nzcnt;                        // flagged-row count
__device__ int   g_nzlist[NROW];                 // flagged rows
// top-k selection scratch
__device__ int   g_hist[KK * 128];
__device__ int   g_bstar[KK];
__device__ int   g_candcnt[KK];
__device__ float g_cand[(size_t)KK * NROW];

// ======================= prep: tv_n + concept_far + zero scratch ========
__global__ void prep_kernel(const float* __restrict__ tv, float* __restrict__ out) {
    __shared__ float cinv[64];
    __shared__ float sd[DD];
    int t = threadIdx.x;                 // 256 threads
    for (int i = t; i < KK * 128; i += 256) g_hist[i] = 0;
    if (t < KK) g_candcnt[t] = 0;
    if (t == 0) g_nzcnt = 0;
    if (t < KK) {
        float s = 0.f;
        for (int d = 0; d < DD; d++) { float v = tv[d * KK + t]; s += v * v; }
        cinv[t] = 1.0f / fmaxf(sqrtf(s), 1e-12f);
    }
    __syncthreads();
    {   // thread t == d
        float sum = 0.f;
        for (int k = 0; k < KK; k++) {
            float v = tv[t * KK + k] * cinv[k];
            g_tvn[t * KK + k] = v;
            sum += v;
        }
        sd[t] = sum;
    }
    __syncthreads();
    if (t == 0) {
        float g = 0.f;
        for (int d = 0; d < DD; d++) g += sd[d] * sd[d];
        out[OUT_CFAR] = (g - (float)KK) / (float)(KK * KK);
        out[OUT_ZERO] = 0.0f;
    }
}

// ================= zero kernels (launch idx 1,2 before kernelA) =========
__global__ void zeroCorr() {            // 64 x 256 -> 65536/16384... grid-stride
    for (int i = blockIdx.x * 256 + threadIdx.x; i < NROW; i += gridDim.x * 256)
        g_corr[i] = 0.f;
}
__global__ void zeroHsum() {            // 128 x 256
    g_hsum[blockIdx.x * 256 + threadIdx.x] = 0.f;
}

// =================== kernelA: topic path (rec1 phase removed) ===========
#define XS_F  (256 * 128)
#define TVS_F (256 * 52)
#define TPS_F (128 * 52)
#define SMEM_A_BYTES ((XS_F + TVS_F + TPS_F + 128 + 512) * 4)

__global__ void __launch_bounds__(512) kernelA(const float* __restrict__ fin,
                                               float* __restrict__ out) {
    extern __shared__ float sm[];
    float* xs  = sm;                   // [256 d][128 j]
    float* tvs = xs + XS_F;            // [256 d][52 k]; dead after GEMM -> hist
    float* tps = tvs + TVS_F;          // [128 j][52 k]
    float* rn  = tps + TPS_F;          // [128] r, later inv-denominator
    float* ps  = rn + 128;             // [128][4]

    int t = threadIdx.x;
    int cid = blockIdx.x;
    int b = cid >> 2, st = cid & 3;
    int s0 = st * 128;
    int row0 = b * SS + s0;            // == cid*128
    const float* fb = fin + (size_t)b * DD * SS + s0;

    // load x tile (coalesced over s)
    #pragma unroll 4
    for (int it = 0; it < 64; it++) {
        int idx = t + 512 * it;
        int d = idx >> 7, j = idx & 127;
        xs[d * 128 + j] = fb[(size_t)d * SS + j];
    }
    // load tv_n padded to 52 cols
    for (int idx = t; idx < TVS_F; idx += 512) {
        int d = idx / 52, k = idx - d * 52;
        tvs[idx] = (k < KK) ? g_tvn[d * KK + k] : 0.0f;
    }
    __syncthreads();

    // row norms: 4 threads per row
    {
        int j = t >> 2, q = t & 3;
        const float* xp = xs + (q * 64) * 128 + j;
        float s = 0.f;
        #pragma unroll 8
        for (int d = 0; d < 64; d++) { float v = xp[d * 128]; s += v * v; }
        ps[j * 4 + q] = s;
    }
    __syncthreads();
    if (t < 128) {
        float s = ps[t * 4] + ps[t * 4 + 1] + ps[t * 4 + 2] + ps[t * 4 + 3];
        float r = 1.0f / fmaxf(sqrtf(s), 1e-12f);
        rn[t] = r;
        g_rnorm[row0 + t] = r;
        // ||xn||^2 = ssq * r^2 — ae base term; warp-reduce across the 4 warps
        float xn2 = s * r * r;
        #pragma unroll
        for (int off = 16; off >= 1; off >>= 1)
            xn2 += __shfl_xor_sync(0xffffffffu, xn2, off);
        if ((t & 31) == 0) ps[t >> 5] = xn2;   // ps[0..3]
    }
    __syncthreads();
    if (t == 0) g_aepartA[cid] = ps[0] + ps[1] + ps[2] + ps[3];

    // topic dots: 32 j-tiles x 13 k-tiles, 4x4 register tiles
    if (t < 416) {
        int jt = t / 13, kt = t - jt * 13;
        const float* xb = xs + jt * 4;
        const float* tb = tvs + kt * 4;
        float acc[4][4] = {};
        #pragma unroll 4
        for (int d = 0; d < DD; d++) {
            float4 xv = *(const float4*)(xb + d * 128);
            float4 tw = *(const float4*)(tb + d * 52);
            float xr[4] = {xv.x, xv.y, xv.z, xv.w};
            float tr[4] = {tw.x, tw.y, tw.z, tw.w};
            #pragma unroll
            for (int r = 0; r < 4; r++)
                #pragma unroll
                for (int c = 0; c < 4; c++)
                    acc[r][c] += xr[r] * tr[c];
        }
        #pragma unroll
        for (int r = 0; r < 4; r++)
            #pragma unroll
            for (int c = 0; c < 4; c++)
                tps[(jt * 4 + r) * 52 + kt * 4 + c] = acc[r][c];
    }
    __syncthreads();

    // tvs is dead -> reuse as local histogram
    int* hist = (int*)tvs;
    for (int i = t; i < KK * 128; i += 512) hist[i] = 0;
    __syncthreads();

    // mask / sum / tpnT / hist: 4 threads per row
    int j = t >> 2, q = t & 3;
    int gRow = row0 + j;
    {
        float partial = 0.f;
        float rj = rn[j];
        #pragma unroll
        for (int i = 0; i < 13; i++) {
            int k = q + 4 * i;
            if (k < KK) {
                float tp = tps[j * 52 + k];
                float tpn = tp * rj;
                g_tpnT[(size_t)k * NROW + gRow] = tpn;
                int bin = (int)(tpn * 128.0f);
                if (bin >= 8) atomicAdd(&hist[k * 128 + min(bin, 127)], 1);
                float m = (tpn > 0.3f) ? tp : 0.0f;
                tps[j * 52 + k] = m;
                partial += m;
            }
        }
        ps[j * 4 + q] = partial;
    }
    __syncthreads();
    if (t < 128) {
        float s = ps[t * 4] + ps[t * 4 + 1] + ps[t * 4 + 2] + ps[t * 4 + 3];
        rn[t] = 1.0f / (s + 0.001f + 1e-8f);
        if (s != 0.0f) {                       // flagged row (masked vals > 0)
            int idx = atomicAdd(&g_nzcnt, 1);
            g_nzlist[idx] = row0 + t;
        }
    }
    __syncthreads();
    {
        float inv = rn[j];
        #pragma unroll
        for (int i = 0; i < 13; i++) {
            int k = q + 4 * i;
            if (k < KK) tps[j * 52 + k] *= inv;
        }
    }
    __syncthreads();

    // flat coalesced tpnn copy: this CTA's output region is contiguous
    {
        float* tpnn = out + OUT_TPNN + (size_t)row0 * KK;
        for (int i = t; i < 128 * KK; i += 512) {
            int r_ = i / KK, k_ = i - r_ * KK;
            tpnn[i] = tps[r_ * 52 + k_];
        }
    }
    // flush local histogram
    for (int i = t; i < KK * 128; i += 512) {
        int c = hist[i];
        if (c) atomicAdd(&g_hist[i], c);
    }
}

// ====== kernelR: sparse rows — fp32 rec1/rec2 + ae correction + hsum ====
__global__ void __launch_bounds__(256) kernelR(const float* __restrict__ fin,
                                               const float* __restrict__ rec1,
                                               const float* __restrict__ rec2,
                                               const float* __restrict__ out) {
    __shared__ float nn[52];
    __shared__ float r1[HH];
    __shared__ float red[256];
    int t = threadIdx.x;
    int cnt = g_nzcnt;
    const float* tpnn = out + OUT_TPNN;
    for (int i = blockIdx.x; i < cnt; i += gridDim.x) {
        int row = g_nzlist[i];
        int b = row >> 9, s = row & 511;
        if (t < KK) nn[t] = tpnn[(size_t)row * KK + t];
        __syncthreads();
        float z = 0.f;
        #pragma unroll 5
        for (int k = 0; k < KK; k++) z += nn[k] * rec1[k * HH + t];
        z = fmaxf(z, 0.f);
        r1[t] = z;
        atomicAdd(&g_hsum[b * HH + t], z);
        __syncthreads();
        float o = 0.f;
        #pragma unroll 8
        for (int h = 0; h < HH; h++) o += r1[h] * rec2[h * DD + t];
        float xn = fin[(size_t)b * DD * SS + (size_t)t * SS + s] * g_rnorm[row];
        red[t] = o * o - 2.0f * xn * o;
        __syncthreads();
        for (int off = 128; off > 0; off >>= 1) {
            if (t < off) red[t] += red[t + off];
            __syncthreads();
        }
        if (t == 0) g_corr[row] = red[0];
        __syncthreads();    // protect nn/r1 reuse across iterations
    }
}

// =========== top-k chain: threshold -> collect -> select ================
__global__ void threshK() {
    int k = blockIdx.x;
    int lane = threadIdx.x;
    int cum = 0, bstar = 7;
    for (int base = 127; base >= 8 && bstar == 7; base -= 32) {
        int bb = base - lane;
        int cnt = (bb >= 8) ? g_hist[k * 128 + bb] : 0;
        int incl = cnt;
        #pragma unroll
        for (int off = 1; off < 32; off <<= 1) {
            int v = __shfl_up_sync(0xffffffffu, incl, off);
            if (lane >= off) incl += v;
        }
        int total = __shfl_sync(0xffffffffu, incl, 31);
        unsigned mask = __ballot_sync(0xffffffffu, (cum + incl >= 32) && bb >= 8);
        if (mask) bstar = base - (__ffs(mask) - 1);
        cum += total;
    }
    if (lane == 0) g_bstar[k] = bstar;
}

__global__ void __launch_bounds__(256) collectK() {
    int t = threadIdx.x;
    int row0 = blockIdx.x * 256;
    #pragma unroll 2
    for (int k = 0; k < KK; k++) {
        float v = g_tpnT[(size_t)k * NROW + row0 + t];
        int bin = (int)(v * 128.0f);
        int bs = g_bstar[k];
        if (bin >= bs || bs == 7) {
            int idx = atomicAdd(&g_candcnt[k], 1);
            g_cand[(size_t)k * NROW + idx] = v;
        }
    }
}

__global__ void __launch_bounds__(256) finalC() {
    int k = blockIdx.x, t = threadIdx.x;
    int C = g_candcnt[k];
    __shared__ float vals[8192];
    __shared__ float rmax[256];
    __shared__ int   rarg[256];
    float* v;
    if (C <= 8192) {
        for (int i = t; i < C; i += 256) vals[i] = g_cand[(size_t)k * NROW + i];
        v = vals;
    } else {
        v = &g_cand[(size_t)k * NROW];
    }
    __syncthreads();
    float sum = 0.f;
    int rounds = C < 32 ? C : 32;
    for (int r = 0; r < rounds; r++) {
        float m = -1e30f; int mi = -1;
        for (int i = t; i < C; i += 256) {
            float x = v[i];
            if (x > m) { m = x; mi = i; }
        }
        rmax[t] = m; rarg[t] = mi;
        __syncthreads();
        for (int off = 128; off > 0; off >>= 1) {
            if (t < off && rmax[t + off] > rmax[t]) { rmax[t] = rmax[t + off]; rarg[t] = rarg[t + off]; }
            __syncthreads();
        }
        if (t == 0) { sum += rmax[0]; v[rarg[0]] = -1e30f; }
        __syncthreads();
    }
    if (t == 0) g_topsum[k] = sum;
}

// ============ predK: rowrec[b][d] = hsum[b] @ rec2 (fp32 exact) =========
__global__ void __launch_bounds__(256) predK(const float* __restrict__ rec2) {
    __shared__ float hs[HH];
    int b = blockIdx.x, d = threadIdx.x;
    hs[d] = g_hsum[b * HH + d];
    __syncthreads();
    float acc = 0.f;
    #pragma unroll 8
    for (int h = 0; h < HH; h++) acc += hs[h] * rec2[h * DD + d];
    g_rowrec[b * DD + d] = acc;
}

// =================== final: ae + csim + pred head =======================
__global__ void __launch_bounds__(256) finalK(const float* __restrict__ Wc,
                                              const float* __restrict__ bc,
                                              float* __restrict__ out) {
    __shared__ float red[256];
    int t = threadIdx.x;
    float s = 0.f;
    for (int i = t; i < NROW; i += 256) s += g_corr[i];
    for (int i = t; i < 512; i += 256) s += g_aepartA[i];
    red[t] = s;
    __syncthreads();
    for (int off = 128; off > 0; off >>= 1) {
        if (t < off) red[t] += red[t + off];
        __syncthreads();
    }
    if (t == 0) {
        out[OUT_AE] = red[0] / 16777216.0f;
        float cs = 0.f;
        for (int k = 0; k < KK; k++) cs += g_topsum[k];
        out[OUT_CSIM] = -cs / 1600.0f;
    }
    {
        int bi = t >> 1, c = t & 1;
        float acc = 0.f;
        for (int d = 0; d < DD; d++)
            acc += g_rowrec[bi * DD + d] * Wc[d * 2 + c];
        out[bi * 2 + c] = acc * (1.0f / 512.0f) + bc[c];
    }
}

// ============================ launcher ===================================
extern "C" void kernel_launch(void* const* d_in, const int* in_sizes, int n_in,
                              void* d_out, int out_size) {
    const float* f_input      = (const float*)d_in[0];
    const float* topic_vector = (const float*)d_in[2];
    const float* rec1         = (const float*)d_in[3];
    const float* rec2         = (const float*)d_in[4];
    const float* Wc           = (const float*)d_in[5];
    const float* bc           = (const float*)d_in[6];
    float* out = (float*)d_out;

    cudaFuncSetAttribute(kernelA, cudaFuncAttributeMaxDynamicSharedMemorySize, SMEM_A_BYTES);

    prep_kernel<<<1, 256>>>(topic_vector, out);        // idx 0
    zeroCorr<<<64, 256>>>();                           // idx 1
    zeroHsum<<<128, 256>>>();                          // idx 2
    kernelA<<<512, 512, SMEM_A_BYTES>>>(f_input, out); // idx 3 -> profiled
    kernelR<<<128, 256>>>(f_input, rec1, rec2, out);
    threshK<<<KK, 32>>>();
    collectK<<<256, 256>>>();
    finalC<<<KK, 256>>>();
    predK<<<BB, 256>>>(rec2);
    finalK<<<1, 256>>>(Wc, bc, out);
}

// round 9
// speedup vs baseline: 2.6640x; 1.0804x over previous
#include <cuda_runtime.h>
#include <cuda_bf16.h>
#include <math.h>
#include <stdint.h>

// Problem constants
#define BB   128
#define DD   256
#define SS   512
#define KK   50
#define HH   256
#define NROW 65536           // B*S
#define OUT_PRED   0         // 256 floats
#define OUT_ZERO   256
#define OUT_CSIM   257
#define OUT_CFAR   258
#define OUT_TPNN   259       // 3,276,800 floats (ODD offset: scalar stores only!)
#define OUT_AE     3277059

// -------- scratch (static device memory; no allocations allowed) --------
__device__ float g_tvn[DD * KK];                 // normalized topic vectors [d][k]
__device__ float g_rnorm[NROW];                  // 1/max(||x||,1e-12) per row
__device__ float g_tpnT[(size_t)KK * NROW];      // APPROX tpn transposed [k][row]
__device__ float g_aepartA[512];                 // per-kernelA-CTA sum of ||xn||^2
__device__ float g_corr[NROW];                   // per-row ae correction (sparse)
__device__ float g_hsum[BB * HH];                // sum_s relu(nn@rec1) per batch
__device__ float g_rowrec[BB * DD];              // hsum @ rec2
__device__ float g_topsum[KK];                   // per-concept top-32 sums
__device__ int   g_nzcnt;                        // flagged-row count
__device__ int   g_nzlist[NROW];                 // flagged rows
// top-k selection scratch
__device__ int   g_hist[KK * 128];
__device__ int   g_bstar[KK];
__device__ int   g_candcnt[KK];
__device__ float g_cand[(size_t)KK * NROW];

// ---------------- tf32 helpers ----------------
__device__ __forceinline__ uint32_t tf32cvt(float x) {
    uint32_t r;
    asm("cvt.rna.tf32.f32 %0, %1;" : "=r"(r) : "f"(x));
    return r;
}
__device__ __forceinline__ void mma_tf32(float* c, uint32_t a0, uint32_t a1,
                                         uint32_t a2, uint32_t a3,
                                         uint32_t b0, uint32_t b1) {
    asm volatile(
        "mma.sync.aligned.m16n8k8.row.col.f32.tf32.tf32.f32 "
        "{%0,%1,%2,%3},{%4,%5,%6,%7},{%8,%9},{%0,%1,%2,%3};"
        : "+f"(c[0]), "+f"(c[1]), "+f"(c[2]), "+f"(c[3])
        : "r"(a0), "r"(a1), "r"(a2), "r"(a3), "r"(b0), "r"(b1));
}

// ======================= prep: tv_n + concept_far + zero scratch ========
__global__ void prep_kernel(const float* __restrict__ tv, float* __restrict__ out) {
    __shared__ float cinv[64];
    __shared__ float sd[DD];
    int t = threadIdx.x;                 // 256 threads
    for (int i = t; i < KK * 128; i += 256) g_hist[i] = 0;
    if (t < KK) g_candcnt[t] = 0;
    if (t == 0) g_nzcnt = 0;
    if (t < KK) {
        float s = 0.f;
        for (int d = 0; d < DD; d++) { float v = tv[d * KK + t]; s += v * v; }
        cinv[t] = 1.0f / fmaxf(sqrtf(s), 1e-12f);
    }
    __syncthreads();
    {   // thread t == d
        float sum = 0.f;
        for (int k = 0; k < KK; k++) {
            float v = tv[t * KK + k] * cinv[k];
            g_tvn[t * KK + k] = v;
            sum += v;
        }
        sd[t] = sum;
    }
    __syncthreads();
    if (t == 0) {
        float g = 0.f;
        for (int d = 0; d < DD; d++) g += sd[d] * sd[d];
        out[OUT_CFAR] = (g - (float)KK) / (float)(KK * KK);
        out[OUT_ZERO] = 0.0f;
    }
}

// ================= zero kernels =========================================
__global__ void zeroCorr() {
    for (int i = blockIdx.x * 256 + threadIdx.x; i < NROW; i += gridDim.x * 256)
        g_corr[i] = 0.f;
}
__global__ void zeroHsum() {
    g_hsum[blockIdx.x * 256 + threadIdx.x] = 0.f;
}

// =================== kernelA: tf32 tensor-core topic path ===============
// 512 CTAs x 256 threads; 128-row tile. smem:
//   xs  [128 j][261]  tf32-as-float (stride 261: col access conflict-free)
//   tvs [256 d][56]   tf32 tvn^T padded (stride 56: B-frag conflict-free)
#define XS_STR  261
#define TVN_STR 56
#define A_SMEM_F (128 * XS_STR + 256 * TVN_STR + 128 + 8 + 256 + 128 + KK * 128)
#define A_SMEM_BYTES (A_SMEM_F * 4)

__global__ void __launch_bounds__(256) kernelA(const float* __restrict__ fin,
                                               float* __restrict__ out) {
    extern __shared__ float sm[];
    float* xs   = sm;                         // 33408
    float* tvs  = xs + 128 * XS_STR;          // 14336
    float* rn   = tvs + 256 * TVN_STR;        // 128
    float* red8 = rn + 128;                   // 8
    float* ssqp = red8 + 8;                   // 256 ([j][2])
    float* flg  = ssqp + 256;                 // 128
    int*   hloc = (int*)(flg + 128);          // 6400

    int t = threadIdx.x;
    int cid = blockIdx.x;
    int b = cid >> 2, st = cid & 3;
    int s0 = st * 128;
    int row0 = cid * 128;
    const float* fb = fin + (size_t)b * DD * SS + s0;

    // load tvn^T (tf32), zero hist/flags
    for (int i = t; i < 256 * TVN_STR; i += 256) {
        int d = i / TVN_STR, k = i - d * TVN_STR;
        float v = (k < KK) ? g_tvn[d * KK + k] : 0.0f;
        tvs[i] = __uint_as_float(tf32cvt(v));
    }
    for (int i = t; i < KK * 128; i += 256) hloc[i] = 0;
    if (t < 128) flg[t] = 0.f;

    // load x tile: j = t&127 fixed, halves of d per thread; ssq in fp32
    {
        int j = t & 127, hf = t >> 7;
        float ssq = 0.f;
        #pragma unroll 8
        for (int it = 0; it < 128; it++) {
            int d = hf + 2 * it;
            float v = fb[(size_t)d * SS + j];
            ssq = fmaf(v, v, ssq);
            xs[j * XS_STR + d] = __uint_as_float(tf32cvt(v));
        }
        ssqp[j * 2 + hf] = ssq;
    }
    __syncthreads();

    // row norms (exact fp32) + ae base term
    if (t < 128) {
        float s = ssqp[2 * t] + ssqp[2 * t + 1];
        float r = 1.0f / fmaxf(sqrtf(s), 1e-12f);
        rn[t] = r;
        g_rnorm[row0 + t] = r;
        float xn2 = s * r * r;
        #pragma unroll
        for (int off = 16; off >= 1; off >>= 1)
            xn2 += __shfl_xor_sync(0xffffffffu, xn2, off);
        if ((t & 31) == 0) red8[t >> 5] = xn2;
    }
    __syncthreads();
    if (t == 0) g_aepartA[cid] = red8[0] + red8[1] + red8[2] + red8[3];

    // tf32 mma GEMM: tp[128 j][56 k] = xs @ tvs
    int warp = t >> 5, lane = t & 31, g = lane >> 2, tid = lane & 3;
    int j0 = warp * 16;
    float acc[7][4];
    #pragma unroll
    for (int nt = 0; nt < 7; nt++)
        #pragma unroll
        for (int c = 0; c < 4; c++) acc[nt][c] = 0.f;

    const uint32_t* xsu = (const uint32_t*)xs;
    const uint32_t* tvu = (const uint32_t*)tvs;
    #pragma unroll 2
    for (int d0 = 0; d0 < 256; d0 += 8) {
        uint32_t a0 = xsu[(j0 + g) * XS_STR + d0 + tid];
        uint32_t a1 = xsu[(j0 + 8 + g) * XS_STR + d0 + tid];
        uint32_t a2 = xsu[(j0 + g) * XS_STR + d0 + tid + 4];
        uint32_t a3 = xsu[(j0 + 8 + g) * XS_STR + d0 + tid + 4];
        #pragma unroll
        for (int nt = 0; nt < 7; nt++) {
            uint32_t b0 = tvu[(d0 + tid) * TVN_STR + nt * 8 + g];
            uint32_t b1 = tvu[(d0 + tid + 4) * TVN_STR + nt * 8 + g];
            mma_tf32(acc[nt], a0, a1, a2, a3, b0, b1);
        }
    }

    // epilogue: tpn store (approx), hist, row flags
    #pragma unroll
    for (int nt = 0; nt < 7; nt++) {
        #pragma unroll
        for (int c = 0; c < 4; c++) {
            int jj = j0 + g + ((c >= 2) ? 8 : 0);
            int k = nt * 8 + tid * 2 + (c & 1);
            if (k < KK) {
                float tpn = acc[nt][c] * rn[jj];
                g_tpnT[(size_t)k * NROW + row0 + jj] = tpn;
                int bin = (int)(tpn * 128.0f);
                if (bin >= 8) atomicAdd(&hloc[k * 128 + min(bin, 127)], 1);
                if (tpn > 0.2985f) flg[jj] = 1.f;   // 1.5e-3 margin (tf32 wc 1e-3)
            }
        }
    }
    __syncthreads();
    if (t < 128 && flg[t] != 0.f) {
        int idx = atomicAdd(&g_nzcnt, 1);
        g_nzlist[idx] = row0 + t;
    }
    // tpnn zeros for all rows (flagged rows overwritten exactly by kernelR)
    {
        float* tpnn = out + OUT_TPNN + (size_t)row0 * KK;
        for (int i = t; i < 128 * KK; i += 256) tpnn[i] = 0.f;
    }
    // flush histogram
    for (int i = t; i < KK * 128; i += 256) {
        int c = hloc[i];
        if (c) atomicAdd(&g_hist[i], c);
    }
}

// ====== kernelR: flagged rows — EXACT fp32 everything ===================
__global__ void __launch_bounds__(256) kernelR(const float* __restrict__ fin,
                                               const float* __restrict__ rec1,
                                               const float* __restrict__ rec2,
                                               float* __restrict__ out) {
    __shared__ float xrow[DD];
    __shared__ float msk[KK];
    __shared__ float nn[KK];
    __shared__ float r1[HH];
    __shared__ float red[256];
    __shared__ float inv_s;
    int t = threadIdx.x;
    int cnt = g_nzcnt;
    float* tpnn_out = out + OUT_TPNN;
    for (int i = blockIdx.x; i < cnt; i += gridDim.x) {
        int row = g_nzlist[i];
        int b = row >> 9, s = row & 511;
        float r = g_rnorm[row];
        xrow[t] = fin[(size_t)b * DD * SS + (size_t)t * SS + s];
        __syncthreads();
        if (t < KK) {
            float tp = 0.f;
            #pragma unroll 8
            for (int d = 0; d < DD; d++) tp += xrow[d] * g_tvn[d * KK + t];
            msk[t] = ((tp * r) > 0.3f) ? tp : 0.f;   // EXACT mask decision
        }
        __syncthreads();
        if (t == 0) {
            float su = 0.f;
            for (int k = 0; k < KK; k++) su += msk[k];
            inv_s = 1.0f / (su + 0.001f + 1e-8f);
        }
        __syncthreads();
        if (t < KK) {
            float v = msk[t] * inv_s;
            nn[t] = v;
            tpnn_out[(size_t)row * KK + t] = v;      // exact tpnn
        }
        __syncthreads();
        float z = 0.f;
        #pragma unroll 5
        for (int k = 0; k < KK; k++) z += nn[k] * rec1[k * HH + t];
        z = fmaxf(z, 0.f);
        r1[t] = z;
        atomicAdd(&g_hsum[b * HH + t], z);
        __syncthreads();
        float o = 0.f;
        #pragma unroll 8
        for (int h = 0; h < HH; h++) o += r1[h] * rec2[h * DD + t];
        float xn = xrow[t] * r;
        red[t] = o * o - 2.0f * xn * o;
        __syncthreads();
        for (int off = 128; off > 0; off >>= 1) {
            if (t < off) red[t] += red[t + off];
            __syncthreads();
        }
        if (t == 0) g_corr[row] = red[0];
        __syncthreads();
    }
}

// =========== top-k chain ================================================
__global__ void threshK() {
    int k = blockIdx.x;
    int lane = threadIdx.x;
    int cum = 0, bstar = 7;
    for (int base = 127; base >= 8 && bstar == 7; base -= 32) {
        int bb = base - lane;
        int cnt = (bb >= 8) ? g_hist[k * 128 + bb] : 0;
        int incl = cnt;
        #pragma unroll
        for (int off = 1; off < 32; off <<= 1) {
            int v = __shfl_up_sync(0xffffffffu, incl, off);
            if (lane >= off) incl += v;
        }
        int total = __shfl_sync(0xffffffffu, incl, 31);
        unsigned mask = __ballot_sync(0xffffffffu, (cum + incl >= 32) && bb >= 8);
        if (mask) bstar = base - (__ffs(mask) - 1);
        cum += total;
    }
    if (lane == 0) g_bstar[k] = bstar;
}

// collect with ONE-BIN margin (bstar-1): covers tf32 approx error (<=2e-3 << 7.8e-3)
__global__ void __launch_bounds__(256) collectK() {
    int t = threadIdx.x;
    int row0 = blockIdx.x * 256;
    #pragma unroll 2
    for (int k = 0; k < KK; k++) {
        float v = g_tpnT[(size_t)k * NROW + row0 + t];
        int bin = (int)(v * 128.0f);
        int bs = g_bstar[k];
        if (bin >= bs - 1 || bs == 7) {
            int idx = atomicAdd(&g_candcnt[k], 1);
            g_cand[(size_t)k * NROW + idx] = v;
        }
    }
}

__global__ void __launch_bounds__(256) finalC() {
    int k = blockIdx.x, t = threadIdx.x;
    int C = g_candcnt[k];
    __shared__ float vals[8192];
    __shared__ float rmax[256];
    __shared__ int   rarg[256];
    float* v;
    if (C <= 8192) {
        for (int i = t; i < C; i += 256) vals[i] = g_cand[(size_t)k * NROW + i];
        v = vals;
    } else {
        v = &g_cand[(size_t)k * NROW];
    }
    __syncthreads();
    float sum = 0.f;
    int rounds = C < 32 ? C : 32;
    for (int r = 0; r < rounds; r++) {
        float m = -1e30f; int mi = -1;
        for (int i = t; i < C; i += 256) {
            float x = v[i];
            if (x > m) { m = x; mi = i; }
        }
        rmax[t] = m; rarg[t] = mi;
        __syncthreads();
        for (int off = 128; off > 0; off >>= 1) {
            if (t < off && rmax[t + off] > rmax[t]) { rmax[t] = rmax[t + off]; rarg[t] = rarg[t + off]; }
            __syncthreads();
        }
        if (t == 0) { sum += rmax[0]; v[rarg[0]] = -1e30f; }
        __syncthreads();
    }
    if (t == 0) g_topsum[k] = sum;
}

// ============ predK: rowrec[b][d] = hsum[b] @ rec2 (fp32 exact) =========
__global__ void __launch_bounds__(256) predK(const float* __restrict__ rec2) {
    __shared__ float hs[HH];
    int b = blockIdx.x, d = threadIdx.x;
    hs[d] = g_hsum[b * HH + d];
    __syncthreads();
    float acc = 0.f;
    #pragma unroll 8
    for (int h = 0; h < HH; h++) acc += hs[h] * rec2[h * DD + d];
    g_rowrec[b * DD + d] = acc;
}

// =================== final: ae + csim + pred head =======================
__global__ void __launch_bounds__(256) finalK(const float* __restrict__ Wc,
                                              const float* __restrict__ bc,
                                              float* __restrict__ out) {
    __shared__ float red[256];
    int t = threadIdx.x;
    float s = 0.f;
    for (int i = t; i < NROW; i += 256) s += g_corr[i];
    for (int i = t; i < 512; i += 256) s += g_aepartA[i];
    red[t] = s;
    __syncthreads();
    for (int off = 128; off > 0; off >>= 1) {
        if (t < off) red[t] += red[t + off];
        __syncthreads();
    }
    if (t == 0) {
        out[OUT_AE] = red[0] / 16777216.0f;
        float cs = 0.f;
        for (int k = 0; k < KK; k++) cs += g_topsum[k];
        out[OUT_CSIM] = -cs / 1600.0f;
    }
    {
        int bi = t >> 1, c = t & 1;
        float acc = 0.f;
        for (int d = 0; d < DD; d++)
            acc += g_rowrec[bi * DD + d] * Wc[d * 2 + c];
        out[bi * 2 + c] = acc * (1.0f / 512.0f) + bc[c];
    }
}

// ============================ launcher ===================================
extern "C" void kernel_launch(void* const* d_in, const int* in_sizes, int n_in,
                              void* d_out, int out_size) {
    const float* f_input      = (const float*)d_in[0];
    const float* topic_vector = (const float*)d_in[2];
    const float* rec1         = (const float*)d_in[3];
    const float* rec2         = (const float*)d_in[4];
    const float* Wc           = (const float*)d_in[5];
    const float* bc           = (const float*)d_in[6];
    float* out = (float*)d_out;

    cudaFuncSetAttribute(kernelA, cudaFuncAttributeMaxDynamicSharedMemorySize, A_SMEM_BYTES);

    prep_kernel<<<1, 256>>>(topic_vector, out);          // idx 0
    zeroCorr<<<64, 256>>>();                             // idx 1
    zeroHsum<<<128, 256>>>();                            // idx 2
    kernelA<<<512, 256, A_SMEM_BYTES>>>(f_input, out);   // idx 3 -> profiled
    kernelR<<<128, 256>>>(f_input, rec1, rec2, out);
    threshK<<<KK, 32>>>();
    collectK<<<256, 256>>>();
    finalC<<<KK, 256>>>();
    predK<<<BB, 256>>>(rec2);
    finalK<<<1, 256>>>(Wc, bc, out);
}

// round 10
// speedup vs baseline: 3.1157x; 1.1696x over previous
#include <cuda_runtime.h>
#include <cuda_bf16.h>
#include <math.h>
#include <stdint.h>

// Problem constants
#define BB   128
#define DD   256
#define SS   512
#define KK   50
#define HH   256
#define NROW 65536           // B*S
#define OUT_PRED   0         // 256 floats
#define OUT_ZERO   256
#define OUT_CSIM   257
#define OUT_CFAR   258
#define OUT_TPNN   259       // 3,276,800 floats (ODD offset: scalar stores only!)
#define OUT_AE     3277059

// -------- scratch (static device memory; no allocations allowed) --------
__device__ float g_tvn[DD * KK];                 // normalized topic vectors [d][k]
__device__ float g_tvnT[DD * 56];                // tvn^T tf32-rounded, padded
__device__ float g_rnorm[NROW];                  // 1/max(||x||,1e-12) per row
__device__ float g_tpnT[(size_t)KK * NROW];      // APPROX tpn transposed [k][row]
__device__ float g_aepartA[512];                 // per-kernelA-CTA sum of ||xn||^2
__device__ float g_corr[NROW];                   // per-row ae correction (flagged only)
__device__ float g_hsum[BB * HH];                // sum_s relu(nn@rec1) per batch
__device__ float g_rowrec[BB * DD];              // hsum @ rec2
__device__ float g_topsum[KK];                   // per-concept top-32 sums
__device__ int   g_nzcnt;                        // flagged-row count
__device__ int   g_nzlist[NROW];                 // flagged rows
// top-k selection scratch
__device__ int   g_hist[KK * 128];
__device__ int   g_bstar[KK];
__device__ int   g_candcnt[KK];
__device__ float g_cand[(size_t)KK * NROW];

// ---------------- tf32 helpers ----------------
__device__ __forceinline__ uint32_t tf32cvt(float x) {
    uint32_t r;
    asm("cvt.rna.tf32.f32 %0, %1;" : "=r"(r) : "f"(x));
    return r;
}
__device__ __forceinline__ void mma_tf32(float* c, uint32_t a0, uint32_t a1,
                                         uint32_t a2, uint32_t a3,
                                         uint32_t b0, uint32_t b1) {
    asm volatile(
        "mma.sync.aligned.m16n8k8.row.col.f32.tf32.tf32.f32 "
        "{%0,%1,%2,%3},{%4,%5,%6,%7},{%8,%9},{%0,%1,%2,%3};"
        : "+f"(c[0]), "+f"(c[1]), "+f"(c[2]), "+f"(c[3])
        : "r"(a0), "r"(a1), "r"(a2), "r"(a3), "r"(b0), "r"(b1));
}

// =================== zeroK: all per-launch scratch zeroing ==============
__global__ void zeroK() {
    int t = threadIdx.x, b = blockIdx.x;
    if (b < 128) {
        g_hsum[b * 256 + t] = 0.f;
    } else {
        for (int i = t; i < KK * 128; i += 256) g_hist[i] = 0;
        if (t < KK) g_candcnt[t] = 0;
        if (t == 0) g_nzcnt = 0;
    }
}

// ======================= prep: tv_n + concept_far =======================
__global__ void prep_kernel(const float* __restrict__ tv, float* __restrict__ out) {
    __shared__ float cinv[64];
    __shared__ float sd[DD];
    int t = threadIdx.x;                 // 256 threads
    if (t < KK) {
        float s = 0.f;
        for (int d = 0; d < DD; d++) { float v = tv[d * KK + t]; s += v * v; }
        cinv[t] = 1.0f / fmaxf(sqrtf(s), 1e-12f);
    }
    __syncthreads();
    {   // thread t == d
        float sum = 0.f;
        for (int k = 0; k < KK; k++) {
            float v = tv[t * KK + k] * cinv[k];
            g_tvn[t * KK + k] = v;
            sum += v;
        }
        sd[t] = sum;
    }
    __syncthreads();
    if (t == 0) {
        float g = 0.f;
        for (int d = 0; d < DD; d++) g += sd[d] * sd[d];
        out[OUT_CFAR] = (g - (float)KK) / (float)(KK * KK);
        out[OUT_ZERO] = 0.0f;
    }
}

// ========= tf32T: g_tvnT[d][56] = tf32(tvn^T), padded ====================
__global__ void tf32T() {
    int i = blockIdx.x * 256 + threadIdx.x;   // 56 blocks x 256 = 14336
    int d = i / 56, k = i - d * 56;
    float v = (k < KK) ? g_tvn[d * KK + k] : 0.0f;
    g_tvnT[i] = __uint_as_float(tf32cvt(v));
}

// =================== kernelA: tf32 mma topic path, 512 threads ==========
// 512 CTAs x 512 threads; 128-row tile; warps 0-7: d[0,128), 8-15: d[128,256)
#define XS_STR  261
#define TVN_STR 56
#define A_SMEM_F (128 * XS_STR + 256 * TVN_STR + 128 + 8 + 512 + 128 + KK * 128)
#define A_SMEM_BYTES (A_SMEM_F * 4)

__global__ void __launch_bounds__(512) kernelA(const float* __restrict__ fin,
                                               float* __restrict__ out) {
    extern __shared__ float sm[];
    float* xs   = sm;                         // [128][261]
    float* tvs  = xs + 128 * XS_STR;          // [256][56]
    float* rn   = tvs + 256 * TVN_STR;        // 128
    float* red8 = rn + 128;                   // 8
    float* ssqp = red8 + 8;                   // [128][4]
    float* flg  = ssqp + 512;                 // 128
    int*   hloc = (int*)(flg + 128);          // [50][128]

    int t = threadIdx.x;
    int cid = blockIdx.x;
    int b = cid >> 2, st = cid & 3;
    int s0 = st * 128;
    int row0 = cid * 128;
    const float* fb = fin + (size_t)b * DD * SS + s0;

    // flat coalesced tvs copy (pre-converted tf32)
    for (int i = t; i < 256 * TVN_STR; i += 512) tvs[i] = g_tvnT[i];
    for (int i = t; i < KK * 128; i += 512) hloc[i] = 0;
    if (t < 128) flg[t] = 0.f;

    // x load: j fixed per thread, quarter of d; exact fp32 ssq
    {
        int j = t & 127, q = t >> 7;
        float ssq = 0.f;
        #pragma unroll 8
        for (int it = 0; it < 64; it++) {
            int d = q * 64 + it;
            float v = fb[(size_t)d * SS + j];
            ssq = fmaf(v, v, ssq);
            xs[j * XS_STR + d] = __uint_as_float(tf32cvt(v));
        }
        ssqp[j * 4 + q] = ssq;
    }
    __syncthreads();

    // row norms (exact) + ae base term
    if (t < 128) {
        float s = ssqp[4 * t] + ssqp[4 * t + 1] + ssqp[4 * t + 2] + ssqp[4 * t + 3];
        float r = 1.0f / fmaxf(sqrtf(s), 1e-12f);
        rn[t] = r;
        g_rnorm[row0 + t] = r;
        float xn2 = s * r * r;
        #pragma unroll
        for (int off = 16; off >= 1; off >>= 1)
            xn2 += __shfl_xor_sync(0xffffffffu, xn2, off);
        if ((t & 31) == 0) red8[t >> 5] = xn2;
    }
    __syncthreads();
    if (t == 0) g_aepartA[cid] = red8[0] + red8[1] + red8[2] + red8[3];

    // tf32 mma GEMM, d-split across warp halves
    int warp = t >> 5, lane = t & 31, g = lane >> 2, tid = lane & 3;
    int j0 = (warp & 7) * 16;
    int dbase = (warp >> 3) * 128;
    float acc[7][4];
    #pragma unroll
    for (int nt = 0; nt < 7; nt++)
        #pragma unroll
        for (int c = 0; c < 4; c++) acc[nt][c] = 0.f;

    const uint32_t* xsu = (const uint32_t*)xs;
    const uint32_t* tvu = (const uint32_t*)tvs;
    #pragma unroll 2
    for (int dd = 0; dd < 128; dd += 8) {
        int d0 = dbase + dd;
        uint32_t a0 = xsu[(j0 + g) * XS_STR + d0 + tid];
        uint32_t a1 = xsu[(j0 + 8 + g) * XS_STR + d0 + tid];
        uint32_t a2 = xsu[(j0 + g) * XS_STR + d0 + tid + 4];
        uint32_t a3 = xsu[(j0 + 8 + g) * XS_STR + d0 + tid + 4];
        #pragma unroll
        for (int nt = 0; nt < 7; nt++) {
            uint32_t b0 = tvu[(d0 + tid) * TVN_STR + nt * 8 + g];
            uint32_t b1 = tvu[(d0 + tid + 4) * TVN_STR + nt * 8 + g];
            mma_tf32(acc[nt], a0, a1, a2, a3, b0, b1);
        }
    }
    __syncthreads();                 // all xs reads done
    float* scratch = xs;             // reuse as [128][56] partial buffer
    if (warp >= 8) {
        #pragma unroll
        for (int nt = 0; nt < 7; nt++)
            #pragma unroll
            for (int c = 0; c < 4; c++) {
                int jj = j0 + g + ((c >= 2) ? 8 : 0);
                int k = nt * 8 + tid * 2 + (c & 1);
                scratch[jj * 56 + k] = acc[nt][c];
            }
    }
    __syncthreads();
    if (warp < 8) {
        #pragma unroll
        for (int nt = 0; nt < 7; nt++) {
            #pragma unroll
            for (int c = 0; c < 4; c++) {
                int jj = j0 + g + ((c >= 2) ? 8 : 0);
                int k = nt * 8 + tid * 2 + (c & 1);
                float full = acc[nt][c] + scratch[jj * 56 + k];
                if (k < KK) {
                    float tpn = full * rn[jj];
                    g_tpnT[(size_t)k * NROW + row0 + jj] = tpn;
                    int bin = (int)(tpn * 128.0f);
                    if (bin >= 8) atomicAdd(&hloc[k * 128 + min(bin, 127)], 1);
                    if (tpn > 0.2985f) flg[jj] = 1.f;  // 1.5e-3 margin (tf32 wc 1e-3)
                }
            }
        }
    }
    __syncthreads();
    if (t < 128 && flg[t] != 0.f) {
        int idx = atomicAdd(&g_nzcnt, 1);
        g_nzlist[idx] = row0 + t;
    }
    // tpnn zeros for all rows (flagged rows overwritten exactly by kernelR)
    {
        float* tpnn = out + OUT_TPNN + (size_t)row0 * KK;
        for (int i = t; i < 128 * KK; i += 512) tpnn[i] = 0.f;
    }
    // flush histogram
    for (int i = t; i < KK * 128; i += 512) {
        int c = hloc[i];
        if (c) atomicAdd(&g_hist[i], c);
    }
}

// ====== kernelR: flagged rows — EXACT fp32 everything ===================
__global__ void __launch_bounds__(256) kernelR(const float* __restrict__ fin,
                                               const float* __restrict__ rec1,
                                               const float* __restrict__ rec2,
                                               float* __restrict__ out) {
    __shared__ float xrow[DD];
    __shared__ float msk[KK];
    __shared__ float nn[KK];
    __shared__ float r1[HH];
    __shared__ float red[256];
    __shared__ float inv_s;
    int t = threadIdx.x;
    int cnt = g_nzcnt;
    float* tpnn_out = out + OUT_TPNN;
    for (int i = blockIdx.x; i < cnt; i += gridDim.x) {
        int row = g_nzlist[i];
        int b = row >> 9, s = row & 511;
        float r = g_rnorm[row];
        xrow[t] = fin[(size_t)b * DD * SS + (size_t)t * SS + s];
        __syncthreads();
        if (t < KK) {
            float tp = 0.f;
            #pragma unroll 8
            for (int d = 0; d < DD; d++) tp += xrow[d] * g_tvn[d * KK + t];
            msk[t] = ((tp * r) > 0.3f) ? tp : 0.f;   // EXACT mask decision
        }
        __syncthreads();
        if (t == 0) {
            float su = 0.f;
            for (int k = 0; k < KK; k++) su += msk[k];
            inv_s = 1.0f / (su + 0.001f + 1e-8f);
        }
        __syncthreads();
        if (t < KK) {
            float v = msk[t] * inv_s;
            nn[t] = v;
            tpnn_out[(size_t)row * KK + t] = v;      // exact tpnn
        }
        __syncthreads();
        float z = 0.f;
        #pragma unroll 5
        for (int k = 0; k < KK; k++) z += nn[k] * rec1[k * HH + t];
        z = fmaxf(z, 0.f);
        r1[t] = z;
        atomicAdd(&g_hsum[b * HH + t], z);
        __syncthreads();
        float o = 0.f;
        #pragma unroll 8
        for (int h = 0; h < HH; h++) o += r1[h] * rec2[h * DD + t];
        float xn = xrow[t] * r;
        red[t] = o * o - 2.0f * xn * o;
        __syncthreads();
        for (int off = 128; off > 0; off >>= 1) {
            if (t < off) red[t] += red[t + off];
            __syncthreads();
        }
        if (t == 0) g_corr[row] = red[0];
        __syncthreads();
    }
}

// =========== top-k chain ================================================
__global__ void threshK() {
    int k = blockIdx.x;
    int lane = threadIdx.x;
    int cum = 0, bstar = 7;
    for (int base = 127; base >= 8 && bstar == 7; base -= 32) {
        int bb = base - lane;
        int cnt = (bb >= 8) ? g_hist[k * 128 + bb] : 0;
        int incl = cnt;
        #pragma unroll
        for (int off = 1; off < 32; off <<= 1) {
            int v = __shfl_up_sync(0xffffffffu, incl, off);
            if (lane >= off) incl += v;
        }
        int total = __shfl_sync(0xffffffffu, incl, 31);
        unsigned mask = __ballot_sync(0xffffffffu, (cum + incl >= 32) && bb >= 8);
        if (mask) bstar = base - (__ffs(mask) - 1);
        cum += total;
    }
    if (lane == 0) g_bstar[k] = bstar;
}

// collect with ONE-BIN margin (bstar-1): covers tf32 approx error (<=2e-3 << 7.8e-3)
__global__ void __launch_bounds__(256) collectK() {
    int t = threadIdx.x;
    int row0 = blockIdx.x * 256;
    #pragma unroll 2
    for (int k = 0; k < KK; k++) {
        float v = g_tpnT[(size_t)k * NROW + row0 + t];
        int bin = (int)(v * 128.0f);
        int bs = g_bstar[k];
        if (bin >= bs - 1 || bs == 7) {
            int idx = atomicAdd(&g_candcnt[k], 1);
            g_cand[(size_t)k * NROW + idx] = v;
        }
    }
}

// finalC: one warp per concept, register-resident top-32 sum
__global__ void __launch_bounds__(32) finalC() {
    int k = blockIdx.x, lane = threadIdx.x;
    int C = g_candcnt[k];
    float* src = g_cand + (size_t)k * NROW;
    float sum = 0.f;
    int rounds = C < 32 ? C : 32;
    if (C <= 256) {
        float v[8];
        #pragma unroll
        for (int i = 0; i < 8; i++) {
            int idx = lane + 32 * i;
            v[i] = (idx < C) ? src[idx] : -1e30f;
        }
        for (int r = 0; r < rounds; r++) {
            float m = v[0]; int mi = 0;
            #pragma unroll
            for (int i = 1; i < 8; i++)
                if (v[i] > m) { m = v[i]; mi = i; }
            float bm = m;
            #pragma unroll
            for (int off = 16; off >= 1; off >>= 1)
                bm = fmaxf(bm, __shfl_xor_sync(0xffffffffu, bm, off));
            sum += bm;
            unsigned msk = __ballot_sync(0xffffffffu, m == bm);
            int wl = __ffs(msk) - 1;
            if (lane == wl) v[mi] = -1e30f;
        }
    } else {                                  // pathological fallback
        volatile float* vs = src;
        for (int r = 0; r < rounds; r++) {
            float m = -1e30f; int mi = -1;
            for (int i = lane; i < C; i += 32) {
                float x = vs[i];
                if (x > m) { m = x; mi = i; }
            }
            float bm = m;
            #pragma unroll
            for (int off = 16; off >= 1; off >>= 1)
                bm = fmaxf(bm, __shfl_xor_sync(0xffffffffu, bm, off));
            sum += bm;
            unsigned msk = __ballot_sync(0xffffffffu, m == bm);
            int wl = __ffs(msk) - 1;
            if (lane == wl && mi >= 0) vs[mi] = -1e30f;
            __syncwarp();
        }
    }
    if (lane == 0) g_topsum[k] = sum;
}

// ============ predK: rowrec[b][d] = hsum[b] @ rec2 (fp32 exact) =========
__global__ void __launch_bounds__(256) predK(const float* __restrict__ rec2) {
    __shared__ float hs[HH];
    int b = blockIdx.x, d = threadIdx.x;
    hs[d] = g_hsum[b * HH + d];
    __syncthreads();
    float acc = 0.f;
    #pragma unroll 8
    for (int h = 0; h < HH; h++) acc += hs[h] * rec2[h * DD + d];
    g_rowrec[b * DD + d] = acc;
}

// =================== final: ae + csim + pred head =======================
__global__ void __launch_bounds__(256) finalK(const float* __restrict__ Wc,
                                              const float* __restrict__ bc,
                                              float* __restrict__ out) {
    __shared__ float red[256];
    int t = threadIdx.x;
    int cnt = g_nzcnt;
    float s = 0.f;
    for (int i = t; i < cnt; i += 256) s += g_corr[g_nzlist[i]];  // flagged only
    for (int i = t; i < 512; i += 256) s += g_aepartA[i];
    red[t] = s;
    __syncthreads();
    for (int off = 128; off > 0; off >>= 1) {
        if (t < off) red[t] += red[t + off];
        __syncthreads();
    }
    if (t == 0) {
        out[OUT_AE] = red[0] / 16777216.0f;
        float cs = 0.f;
        for (int k = 0; k < KK; k++) cs += g_topsum[k];
        out[OUT_CSIM] = -cs / 1600.0f;
    }
    {
        int bi = t >> 1, c = t & 1;
        float acc = 0.f;
        for (int d = 0; d < DD; d++)
            acc += g_rowrec[bi * DD + d] * Wc[d * 2 + c];
        out[bi * 2 + c] = acc * (1.0f / 512.0f) + bc[c];
    }
}

// ============================ launcher ===================================
extern "C" void kernel_launch(void* const* d_in, const int* in_sizes, int n_in,
                              void* d_out, int out_size) {
    const float* f_input      = (const float*)d_in[0];
    const float* topic_vector = (const float*)d_in[2];
    const float* rec1         = (const float*)d_in[3];
    const float* rec2         = (const float*)d_in[4];
    const float* Wc           = (const float*)d_in[5];
    const float* bc           = (const float*)d_in[6];
    float* out = (float*)d_out;

    cudaFuncSetAttribute(kernelA, cudaFuncAttributeMaxDynamicSharedMemorySize, A_SMEM_BYTES);

    zeroK<<<129, 256>>>();                               // idx 0
    prep_kernel<<<1, 256>>>(topic_vector, out);          // idx 1
    tf32T<<<56, 256>>>();                                // idx 2
    kernelA<<<512, 512, A_SMEM_BYTES>>>(f_input, out);   // idx 3 -> profiled
    kernelR<<<128, 256>>>(f_input, rec1, rec2, out);
    threshK<<<KK, 32>>>();
    collectK<<<256, 256>>>();
    finalC<<<KK, 32>>>();
    predK<<<BB, 256>>>(rec2);
    finalK<<<1, 256>>>(Wc, bc, out);
}

// round 11
// speedup vs baseline: 3.5392x; 1.1359x over previous
#include <cuda_runtime.h>
#include <cuda_bf16.h>
#include <math.h>
#include <stdint.h>

// Problem constants
#define BB   128
#define DD   256
#define SS   512
#define KK   50
#define HH   256
#define NROW 65536           // B*S
#define OUT_PRED   0         // 256 floats
#define OUT_ZERO   256
#define OUT_CSIM   257
#define OUT_CFAR   258
#define OUT_TPNN   259       // 3,276,800 floats (ODD offset: scalar stores only!)
#define OUT_AE     3277059

// -------- scratch (static device memory; no allocations allowed) --------
__device__ float g_tvn[DD * KK];                 // normalized topic vectors [d][k]
__device__ float g_tvnT[DD * 56];                // tvn^T tf32-rounded, padded
__device__ float g_rnorm[NROW];                  // 1/max(||x||,1e-12) per row
__device__ float g_tpnT[(size_t)KK * NROW];      // APPROX tpn [k][row] (fallback only)
__device__ float g_aepartA[512];                 // per-kernelA-CTA sum of ||xn||^2
__device__ float g_corr[NROW];                   // per-row ae correction (flagged only)
__device__ float g_hsum[BB * HH];                // sum_s relu(nn@rec1) per batch
__device__ float g_topsum[KK];                   // per-concept top-32 sums
__device__ int   g_nzcnt;                        // flagged-row count
__device__ int   g_nzlist[NROW];                 // flagged rows
__device__ int   g_hist[KK * 128];               // tpn histogram
__device__ int   g_candcnt[KK];                  // candidate counts (bin >= 12)
__device__ float g_cand[(size_t)KK * NROW];      // candidate values

// ---------------- tf32 helpers ----------------
__device__ __forceinline__ uint32_t tf32cvt(float x) {
    uint32_t r;
    asm("cvt.rna.tf32.f32 %0, %1;" : "=r"(r) : "f"(x));
    return r;
}
__device__ __forceinline__ void mma_tf32(float* c, uint32_t a0, uint32_t a1,
                                         uint32_t a2, uint32_t a3,
                                         uint32_t b0, uint32_t b1) {
    asm volatile(
        "mma.sync.aligned.m16n8k8.row.col.f32.tf32.tf32.f32 "
        "{%0,%1,%2,%3},{%4,%5,%6,%7},{%8,%9},{%0,%1,%2,%3};"
        : "+f"(c[0]), "+f"(c[1]), "+f"(c[2]), "+f"(c[3])
        : "r"(a0), "r"(a1), "r"(a2), "r"(a3), "r"(b0), "r"(b1));
}

// ===== prepAll: zeroing + tv_n + concept_far + tf32 transpose (1 launch) =
__global__ void prepAll(const float* __restrict__ tv, float* __restrict__ out) {
    int t = threadIdx.x, b = blockIdx.x;
    if (b < 128) {                      // hsum zero
        g_hsum[b * 256 + t] = 0.f;
        return;
    }
    if (b == 128) {                     // hist / counters zero
        for (int i = t; i < KK * 128; i += 256) g_hist[i] = 0;
        if (t < KK) g_candcnt[t] = 0;
        if (t == 0) g_nzcnt = 0;
        return;
    }
    // b == 129: tvn + cfar + tvnT
    __shared__ float cinv[64];
    __shared__ float sd[DD];
    if (t < KK) {
        float s = 0.f;
        for (int d = 0; d < DD; d++) { float v = tv[d * KK + t]; s += v * v; }
        cinv[t] = 1.0f / fmaxf(sqrtf(s), 1e-12f);
    }
    __syncthreads();
    {   // thread t == d
        float sum = 0.f;
        for (int k = 0; k < KK; k++) {
            float v = tv[t * KK + k] * cinv[k];
            g_tvn[t * KK + k] = v;
            g_tvnT[t * 56 + k] = __uint_as_float(tf32cvt(v));
            sum += v;
        }
        for (int k = KK; k < 56; k++) g_tvnT[t * 56 + k] = 0.f;
        sd[t] = sum;
    }
    __syncthreads();
    if (t == 0) {
        float g = 0.f;
        for (int d = 0; d < DD; d++) g += sd[d] * sd[d];
        out[OUT_CFAR] = (g - (float)KK) / (float)(KK * KK);
        out[OUT_ZERO] = 0.0f;
    }
}

// =================== kernelA: tf32 mma topic path, 512 threads ==========
#define XS_STR  261
#define TVN_STR 56
#define CBUF_W  56
#define A_SMEM_F (128 * XS_STR + 256 * TVN_STR + 128 + 8 + 512 + 128 + KK * 128 + KK * CBUF_W + 64)
#define A_SMEM_BYTES (A_SMEM_F * 4)

__global__ void __launch_bounds__(512) kernelA(const float* __restrict__ fin,
                                               float* __restrict__ out) {
    extern __shared__ float sm[];
    float* xs   = sm;                         // [128][261]
    float* tvs  = xs + 128 * XS_STR;          // [256][56]
    float* rn   = tvs + 256 * TVN_STR;        // 128
    float* red8 = rn + 128;                   // 8
    float* ssqp = red8 + 8;                   // [128][4]
    float* flg  = ssqp + 512;                 // 128
    int*   hloc = (int*)(flg + 128);          // [50][128]
    float* cbuf = (float*)(hloc + KK * 128);  // [50][56]
    int*   ccnt = (int*)(cbuf + KK * CBUF_W); // [50] (+pad)

    int t = threadIdx.x;
    int cid = blockIdx.x;
    int b = cid >> 2, st = cid & 3;
    int s0 = st * 128;
    int row0 = cid * 128;
    const float* fb = fin + (size_t)b * DD * SS + s0;

    for (int i = t; i < 256 * TVN_STR; i += 512) tvs[i] = g_tvnT[i];
    for (int i = t; i < KK * 128; i += 512) hloc[i] = 0;
    if (t < 128) flg[t] = 0.f;
    if (t < KK) ccnt[t] = 0;

    // x load: j fixed per thread, quarter of d; exact fp32 ssq
    {
        int j = t & 127, q = t >> 7;
        float ssq = 0.f;
        #pragma unroll 8
        for (int it = 0; it < 64; it++) {
            int d = q * 64 + it;
            float v = fb[(size_t)d * SS + j];
            ssq = fmaf(v, v, ssq);
            xs[j * XS_STR + d] = __uint_as_float(tf32cvt(v));
        }
        ssqp[j * 4 + q] = ssq;
    }
    __syncthreads();

    // row norms (exact) + ae base term
    if (t < 128) {
        float s = ssqp[4 * t] + ssqp[4 * t + 1] + ssqp[4 * t + 2] + ssqp[4 * t + 3];
        float r = 1.0f / fmaxf(sqrtf(s), 1e-12f);
        rn[t] = r;
        g_rnorm[row0 + t] = r;
        float xn2 = s * r * r;
        #pragma unroll
        for (int off = 16; off >= 1; off >>= 1)
            xn2 += __shfl_xor_sync(0xffffffffu, xn2, off);
        if ((t & 31) == 0) red8[t >> 5] = xn2;
    }
    __syncthreads();
    if (t == 0) g_aepartA[cid] = red8[0] + red8[1] + red8[2] + red8[3];

    // tf32 mma GEMM, d-split across warp halves
    int warp = t >> 5, lane = t & 31, g = lane >> 2, tid = lane & 3;
    int j0 = (warp & 7) * 16;
    int dbase = (warp >> 3) * 128;
    float acc[7][4];
    #pragma unroll
    for (int nt = 0; nt < 7; nt++)
        #pragma unroll
        for (int c = 0; c < 4; c++) acc[nt][c] = 0.f;

    const uint32_t* xsu = (const uint32_t*)xs;
    const uint32_t* tvu = (const uint32_t*)tvs;
    #pragma unroll 2
    for (int dd = 0; dd < 128; dd += 8) {
        int d0 = dbase + dd;
        uint32_t a0 = xsu[(j0 + g) * XS_STR + d0 + tid];
        uint32_t a1 = xsu[(j0 + 8 + g) * XS_STR + d0 + tid];
        uint32_t a2 = xsu[(j0 + g) * XS_STR + d0 + tid + 4];
        uint32_t a3 = xsu[(j0 + 8 + g) * XS_STR + d0 + tid + 4];
        #pragma unroll
        for (int nt = 0; nt < 7; nt++) {
            uint32_t b0 = tvu[(d0 + tid) * TVN_STR + nt * 8 + g];
            uint32_t b1 = tvu[(d0 + tid + 4) * TVN_STR + nt * 8 + g];
            mma_tf32(acc[nt], a0, a1, a2, a3, b0, b1);
        }
    }
    __syncthreads();                 // all xs reads done
    float* scratch = xs;             // reuse as [128][56] partial buffer
    if (warp >= 8) {
        #pragma unroll
        for (int nt = 0; nt < 7; nt++)
            #pragma unroll
            for (int c = 0; c < 4; c++) {
                int jj = j0 + g + ((c >= 2) ? 8 : 0);
                int k = nt * 8 + tid * 2 + (c & 1);
                scratch[jj * 56 + k] = acc[nt][c];
            }
    }
    __syncthreads();
    if (warp < 8) {
        #pragma unroll
        for (int nt = 0; nt < 7; nt++) {
            #pragma unroll
            for (int c = 0; c < 4; c++) {
                int jj = j0 + g + ((c >= 2) ? 8 : 0);
                int k = nt * 8 + tid * 2 + (c & 1);
                float full = acc[nt][c] + scratch[jj * 56 + k];
                if (k < KK) {
                    float tpn = full * rn[jj];
                    g_tpnT[(size_t)k * NROW + row0 + jj] = tpn;  // fallback copy
                    int bin = (int)(tpn * 128.0f);
                    if (bin >= 8) atomicAdd(&hloc[k * 128 + min(bin, 127)], 1);
                    if (bin >= 12) {                              // candidate
                        int ci = atomicAdd(&ccnt[k], 1);
                        if (ci < CBUF_W) cbuf[k * CBUF_W + ci] = tpn;
                        else {                                    // rare spill
                            int gi = atomicAdd(&g_candcnt[k], 1);
                            g_cand[(size_t)k * NROW + gi] = tpn;
                        }
                    }
                    if (tpn > 0.2985f) flg[jj] = 1.f;  // 1.5e-3 tf32 margin
                }
            }
        }
    }
    __syncthreads();
    if (t < 128 && flg[t] != 0.f) {
        int idx = atomicAdd(&g_nzcnt, 1);
        g_nzlist[idx] = row0 + t;
    }
    // bulk candidate flush: one atomic per concept
    if (t < KK) {
        int cnt = min(ccnt[t], CBUF_W);
        if (cnt > 0) {
            int base = atomicAdd(&g_candcnt[t], cnt);
            for (int i = 0; i < cnt; i++)
                g_cand[(size_t)t * NROW + base + i] = cbuf[t * CBUF_W + i];
        }
    }
    // tpnn zeros for all rows (flagged rows overwritten exactly by kernelR)
    {
        float* tpnn = out + OUT_TPNN + (size_t)row0 * KK;
        for (int i = t; i < 128 * KK; i += 512) tpnn[i] = 0.f;
    }
    // flush histogram
    for (int i = t; i < KK * 128; i += 512) {
        int c = hloc[i];
        if (c) atomicAdd(&g_hist[i], c);
    }
}

// ====== kernelR: flagged rows — EXACT fp32 everything ===================
__global__ void __launch_bounds__(256) kernelR(const float* __restrict__ fin,
                                               const float* __restrict__ rec1,
                                               const float* __restrict__ rec2,
                                               float* __restrict__ out) {
    __shared__ float xrow[DD];
    __shared__ float msk[KK];
    __shared__ float nn[KK];
    __shared__ float r1[HH];
    __shared__ float red[256];
    __shared__ float inv_s;
    int t = threadIdx.x;
    int cnt = g_nzcnt;
    float* tpnn_out = out + OUT_TPNN;
    for (int i = blockIdx.x; i < cnt; i += gridDim.x) {
        int row = g_nzlist[i];
        int b = row >> 9, s = row & 511;
        float r = g_rnorm[row];
        xrow[t] = fin[(size_t)b * DD * SS + (size_t)t * SS + s];
        __syncthreads();
        if (t < KK) {
            float tp = 0.f;
            #pragma unroll 8
            for (int d = 0; d < DD; d++) tp += xrow[d] * g_tvn[d * KK + t];
            msk[t] = ((tp * r) > 0.3f) ? tp : 0.f;   // EXACT mask decision
        }
        __syncthreads();
        if (t == 0) {
            float su = 0.f;
            for (int k = 0; k < KK; k++) su += msk[k];
            inv_s = 1.0f / (su + 0.001f + 1e-8f);
        }
        __syncthreads();
        if (t < KK) {
            float v = msk[t] * inv_s;
            nn[t] = v;
            tpnn_out[(size_t)row * KK + t] = v;      // exact tpnn
        }
        __syncthreads();
        float z = 0.f;
        #pragma unroll 5
        for (int k = 0; k < KK; k++) z += nn[k] * rec1[k * HH + t];
        z = fmaxf(z, 0.f);
        r1[t] = z;
        atomicAdd(&g_hsum[b * HH + t], z);
        __syncthreads();
        float o = 0.f;
        #pragma unroll 8
        for (int h = 0; h < HH; h++) o += r1[h] * rec2[h * DD + t];
        float xn = xrow[t] * r;
        red[t] = o * o - 2.0f * xn * o;
        __syncthreads();
        for (int off = 128; off > 0; off >>= 1) {
            if (t < off) red[t] += red[t + off];
            __syncthreads();
        }
        if (t == 0) g_corr[row] = red[0];
        __syncthreads();
    }
}

// ====== finalC: bstar + candidate filter + top-32 sum (one block per k) ==
__global__ void __launch_bounds__(256) finalC() {
    int k = blockIdx.x, t = threadIdx.x;
    __shared__ int hcnt[120];
    __shared__ int s_bstar, scnt, sovf;
    __shared__ float svals[2048];
    __shared__ float rmax[256];
    __shared__ int   rarg[256];

    if (t < 120) hcnt[t] = g_hist[k * 128 + 8 + t];
    if (t == 0) { scnt = 0; sovf = 0; }
    __syncthreads();
    if (t == 0) {
        int cum = 0, bstar = 7;
        for (int b = 127; b >= 8; b--) {
            cum += hcnt[b - 8];
            if (cum >= 32) { bstar = b; break; }
        }
        s_bstar = bstar;
    }
    __syncthreads();
    int bstar = s_bstar;
    int thr = bstar - 1;
    bool fast = (bstar != 7) && (thr >= 12);

    if (fast) {
        int C = g_candcnt[k];
        for (int i = t; i < C; i += 256) {
            float v = g_cand[(size_t)k * NROW + i];
            if ((int)(v * 128.0f) >= thr) {
                int idx = atomicAdd(&scnt, 1);
                if (idx < 2048) svals[idx] = v;
                else sovf = 1;
            }
        }
    }
    __syncthreads();
    int mode = (!fast || sovf) ? 2 : ((scnt <= 256) ? 0 : 1);
    int C = min(scnt, 2048);

    if (mode == 0) {
        // warp 0 register-resident selection
        if (t < 32) {
            float v[8];
            #pragma unroll
            for (int i = 0; i < 8; i++) {
                int idx = t + 32 * i;
                v[i] = (idx < C) ? svals[idx] : -1e30f;
            }
            float sum = 0.f;
            int rounds = C < 32 ? C : 32;
            for (int r = 0; r < rounds; r++) {
                float m = v[0]; int mi = 0;
                #pragma unroll
                for (int i = 1; i < 8; i++)
                    if (v[i] > m) { m = v[i]; mi = i; }
                float bm = m;
                #pragma unroll
                for (int off = 16; off >= 1; off >>= 1)
                    bm = fmaxf(bm, __shfl_xor_sync(0xffffffffu, bm, off));
                sum += bm;
                unsigned msk2 = __ballot_sync(0xffffffffu, m == bm);
                int wl = __ffs(msk2) - 1;
                if (t == wl) v[mi] = -1e30f;
            }
            if (t == 0) g_topsum[k] = sum;
        }
    } else {
        // block-wide 32-round argmax: smem list (mode 1) or gmem column (mode 2)
        float* src = (mode == 1) ? svals : (g_tpnT + (size_t)k * NROW);
        int n = (mode == 1) ? C : NROW;
        float sum = 0.f;
        int rounds = n < 32 ? n : 32;
        for (int r = 0; r < rounds; r++) {
            float m = -1e30f; int mi = -1;
            for (int i = t; i < n; i += 256) {
                float x = src[i];
                if (x > m) { m = x; mi = i; }
            }
            rmax[t] = m; rarg[t] = mi;
            __syncthreads();
            for (int off = 128; off > 0; off >>= 1) {
                if (t < off && rmax[t + off] > rmax[t]) {
                    rmax[t] = rmax[t + off]; rarg[t] = rarg[t + off];
                }
                __syncthreads();
            }
            if (t == 0) { sum += rmax[0]; src[rarg[0]] = -1e30f; }
            __syncthreads();
        }
        if (t == 0) g_topsum[k] = sum;
    }
}

// ====== predfinal: pred[b] = (hsum[b] @ rec2) @ Wc / 512 + bc ===========
__global__ void __launch_bounds__(256) predfinal(const float* __restrict__ rec2,
                                                 const float* __restrict__ Wc,
                                                 const float* __restrict__ bc,
                                                 float* __restrict__ out) {
    __shared__ float hs[HH];
    __shared__ float r0[256], r1[256];
    int b = blockIdx.x, t = threadIdx.x;
    hs[t] = g_hsum[b * HH + t];
    __syncthreads();
    float acc = 0.f;
    #pragma unroll 8
    for (int h = 0; h < HH; h++) acc += hs[h] * rec2[h * DD + t];
    r0[t] = acc * Wc[t * 2];
    r1[t] = acc * Wc[t * 2 + 1];
    __syncthreads();
    for (int off = 128; off > 0; off >>= 1) {
        if (t < off) { r0[t] += r0[t + off]; r1[t] += r1[t + off]; }
        __syncthreads();
    }
    if (t == 0) {
        out[b * 2 + 0] = r0[0] * (1.0f / 512.0f) + bc[0];
        out[b * 2 + 1] = r1[0] * (1.0f / 512.0f) + bc[1];
    }
}

// =================== finalK: ae + csim ==================================
__global__ void __launch_bounds__(256) finalK(float* __restrict__ out) {
    __shared__ float red[256];
    int t = threadIdx.x;
    int cnt = g_nzcnt;
    float s = 0.f;
    for (int i = t; i < cnt; i += 256) s += g_corr[g_nzlist[i]];
    for (int i = t; i < 512; i += 256) s += g_aepartA[i];
    red[t] = s;
    __syncthreads();
    for (int off = 128; off > 0; off >>= 1) {
        if (t < off) red[t] += red[t + off];
        __syncthreads();
    }
    if (t == 0) {
        out[OUT_AE] = red[0] / 16777216.0f;
        float cs = 0.f;
        for (int k = 0; k < KK; k++) cs += g_topsum[k];
        out[OUT_CSIM] = -cs / 1600.0f;
    }
}

// ============================ launcher ===================================
extern "C" void kernel_launch(void* const* d_in, const int* in_sizes, int n_in,
                              void* d_out, int out_size) {
    const float* f_input      = (const float*)d_in[0];
    const float* topic_vector = (const float*)d_in[2];
    const float* rec1         = (const float*)d_in[3];
    const float* rec2         = (const float*)d_in[4];
    const float* Wc           = (const float*)d_in[5];
    const float* bc           = (const float*)d_in[6];
    float* out = (float*)d_out;

    cudaFuncSetAttribute(kernelA, cudaFuncAttributeMaxDynamicSharedMemorySize, A_SMEM_BYTES);

    prepAll<<<130, 256>>>(topic_vector, out);            // idx 0
    kernelA<<<512, 512, A_SMEM_BYTES>>>(f_input, out);   // idx 1
    kernelR<<<128, 256>>>(f_input, rec1, rec2, out);     // idx 2
    finalC<<<KK, 256>>>();                               // idx 3 -> profiled
    predfinal<<<BB, 256>>>(rec2, Wc, bc, out);           // idx 4
    finalK<<<1, 256>>>(out);                             // idx 5
}

// round 12
// speedup vs baseline: 4.1291x; 1.1667x over previous
#include <cuda_runtime.h>
#include <cuda_bf16.h>
#include <math.h>
#include <stdint.h>

// Problem constants
#define BB   128
#define DD   256
#define SS   512
#define KK   50
#define HH   256
#define NROW 65536           // B*S
#define OUT_PRED   0         // 256 floats
#define OUT_ZERO   256
#define OUT_CSIM   257
#define OUT_CFAR   258
#define OUT_TPNN   259       // 3,276,800 floats (ODD offset: scalar stores only!)
#define OUT_AE     3277059

// -------- scratch (static device memory; no allocations allowed) --------
__device__ float g_tvn[DD * KK];                 // normalized topic vectors [d][k]
__device__ float g_tvnT[DD * 56];                // tvn^T tf32-rounded, padded
__device__ float g_rnorm[NROW];                  // 1/max(||x||,1e-12) per row
__device__ float g_tpnT[(size_t)KK * NROW];      // APPROX tpn [k][row] (fallback only)
__device__ float g_aepartA[512];                 // per-kernelA-CTA sum of ||xn||^2
__device__ float g_corr[NROW];                   // per-row ae correction (flagged only)
__device__ float g_hsum[BB * HH];                // sum_s relu(nn@rec1) per batch
__device__ float g_topsum[KK];                   // per-concept top-32 sums
__device__ int   g_nzcnt;                        // flagged-row count
__device__ int   g_nzlist[NROW];                 // flagged rows
__device__ int   g_hist[KK * 128];               // tpn histogram
__device__ int   g_candcnt[KK];                  // candidate counts (bin >= 12)
__device__ float g_cand[(size_t)KK * NROW];      // candidate values

// ---------------- tf32 helpers ----------------
__device__ __forceinline__ uint32_t tf32cvt(float x) {
    uint32_t r;
    asm("cvt.rna.tf32.f32 %0, %1;" : "=r"(r) : "f"(x));
    return r;
}
__device__ __forceinline__ void mma_tf32(float* c, uint32_t a0, uint32_t a1,
                                         uint32_t a2, uint32_t a3,
                                         uint32_t b0, uint32_t b1) {
    asm volatile(
        "mma.sync.aligned.m16n8k8.row.col.f32.tf32.tf32.f32 "
        "{%0,%1,%2,%3},{%4,%5,%6,%7},{%8,%9},{%0,%1,%2,%3};"
        : "+f"(c[0]), "+f"(c[1]), "+f"(c[2]), "+f"(c[3])
        : "r"(a0), "r"(a1), "r"(a2), "r"(a3), "r"(b0), "r"(b1));
}

// ===== prepAll: zeroing + tv_n + concept_far + tf32 transpose (1 launch) =
__global__ void prepAll(const float* __restrict__ tv, float* __restrict__ out) {
    int t = threadIdx.x, b = blockIdx.x;
    if (b < 128) {                      // hsum zero
        g_hsum[b * 256 + t] = 0.f;
        return;
    }
    if (b == 128) {                     // hist / counters zero
        for (int i = t; i < KK * 128; i += 256) g_hist[i] = 0;
        if (t < KK) g_candcnt[t] = 0;
        if (t == 0) g_nzcnt = 0;
        return;
    }
    // b == 129: tvn + cfar + tvnT
    __shared__ float cinv[64];
    __shared__ float sd[DD];
    if (t < KK) {
        float s = 0.f;
        for (int d = 0; d < DD; d++) { float v = tv[d * KK + t]; s += v * v; }
        cinv[t] = 1.0f / fmaxf(sqrtf(s), 1e-12f);
    }
    __syncthreads();
    {   // thread t == d
        float sum = 0.f;
        for (int k = 0; k < KK; k++) {
            float v = tv[t * KK + k] * cinv[k];
            g_tvn[t * KK + k] = v;
            g_tvnT[t * 56 + k] = __uint_as_float(tf32cvt(v));
            sum += v;
        }
        for (int k = KK; k < 56; k++) g_tvnT[t * 56 + k] = 0.f;
        sd[t] = sum;
    }
    __syncthreads();
    if (t == 0) {
        float g = 0.f;
        for (int d = 0; d < DD; d++) g += sd[d] * sd[d];
        out[OUT_CFAR] = (g - (float)KK) / (float)(KK * KK);
        out[OUT_ZERO] = 0.0f;
    }
}

// =================== kernelA: tf32 mma topic path, 512 threads ==========
#define XS_STR  261
#define TVN_STR 56
#define CBUF_W  56
#define A_SMEM_F (128 * XS_STR + 256 * TVN_STR + 128 + 8 + 512 + 128 + KK * 128 + KK * CBUF_W + 64)
#define A_SMEM_BYTES (A_SMEM_F * 4)

__global__ void __launch_bounds__(512) kernelA(const float* __restrict__ fin,
                                               float* __restrict__ out) {
    extern __shared__ float sm[];
    float* xs   = sm;                         // [128][261]
    float* tvs  = xs + 128 * XS_STR;          // [256][56]
    float* rn   = tvs + 256 * TVN_STR;        // 128
    float* red8 = rn + 128;                   // 8
    float* ssqp = red8 + 8;                   // 512 (unused now; kept for layout)
    float* flg  = ssqp + 512;                 // 128
    int*   hloc = (int*)(flg + 128);          // [50][128]; first also ssq scratch
    float* cbuf = (float*)(hloc + KK * 128);  // [50][56]
    int*   ccnt = (int*)(cbuf + KK * CBUF_W); // [50] (+pad)

    int t = threadIdx.x;
    int cid = blockIdx.x;
    int b = cid >> 2, st = cid & 3;
    int s0 = st * 128;
    int row0 = cid * 128;
    const float* fb = fin + (size_t)b * DD * SS + s0;

    for (int i = t; i < 256 * TVN_STR; i += 512) tvs[i] = g_tvnT[i];
    if (t < 128) flg[t] = 0.f;
    if (t < KK) ccnt[t] = 0;

    // x load: float4 along s (warp w owns d = w + 16*i); ssq partials -> hloc scratch
    {
        int w = t >> 5, l = t & 31;
        float ssq4[4] = {0.f, 0.f, 0.f, 0.f};
        #pragma unroll 4
        for (int i = 0; i < 16; i++) {
            int d = w + 16 * i;
            float4 v = *(const float4*)(fb + (size_t)d * SS + l * 4);
            ssq4[0] = fmaf(v.x, v.x, ssq4[0]);
            ssq4[1] = fmaf(v.y, v.y, ssq4[1]);
            ssq4[2] = fmaf(v.z, v.z, ssq4[2]);
            ssq4[3] = fmaf(v.w, v.w, ssq4[3]);
            xs[(l * 4 + 0) * XS_STR + d] = __uint_as_float(tf32cvt(v.x));
            xs[(l * 4 + 1) * XS_STR + d] = __uint_as_float(tf32cvt(v.y));
            xs[(l * 4 + 2) * XS_STR + d] = __uint_as_float(tf32cvt(v.z));
            xs[(l * 4 + 3) * XS_STR + d] = __uint_as_float(tf32cvt(v.w));
        }
        float* sw = (float*)hloc;            // [128][17]
        #pragma unroll
        for (int c = 0; c < 4; c++) sw[(l * 4 + c) * 17 + w] = ssq4[c];
    }
    __syncthreads();

    // row norms (exact fp32) + ae base term
    if (t < 128) {
        float* sw = (float*)hloc;
        float s = 0.f;
        #pragma unroll
        for (int i = 0; i < 16; i++) s += sw[t * 17 + i];
        float r = 1.0f / fmaxf(sqrtf(s), 1e-12f);
        rn[t] = r;
        g_rnorm[row0 + t] = r;
        float xn2 = s * r * r;
        #pragma unroll
        for (int off = 16; off >= 1; off >>= 1)
            xn2 += __shfl_xor_sync(0xffffffffu, xn2, off);
        if ((t & 31) == 0) red8[t >> 5] = xn2;
    }
    __syncthreads();
    if (t == 0) g_aepartA[cid] = red8[0] + red8[1] + red8[2] + red8[3];
    // zero hloc (ssq scratch consumed); visible to epilogue via later syncs
    for (int i = t; i < KK * 128; i += 512) hloc[i] = 0;

    // tf32 mma GEMM, d-split across warp halves
    int warp = t >> 5, lane = t & 31, g = lane >> 2, tid = lane & 3;
    int j0 = (warp & 7) * 16;
    int dbase = (warp >> 3) * 128;
    float acc[7][4];
    #pragma unroll
    for (int nt = 0; nt < 7; nt++)
        #pragma unroll
        for (int c = 0; c < 4; c++) acc[nt][c] = 0.f;

    const uint32_t* xsu = (const uint32_t*)xs;
    const uint32_t* tvu = (const uint32_t*)tvs;
    #pragma unroll 2
    for (int dd = 0; dd < 128; dd += 8) {
        int d0 = dbase + dd;
        uint32_t a0 = xsu[(j0 + g) * XS_STR + d0 + tid];
        uint32_t a1 = xsu[(j0 + 8 + g) * XS_STR + d0 + tid];
        uint32_t a2 = xsu[(j0 + g) * XS_STR + d0 + tid + 4];
        uint32_t a3 = xsu[(j0 + 8 + g) * XS_STR + d0 + tid + 4];
        #pragma unroll
        for (int nt = 0; nt < 7; nt++) {
            uint32_t b0 = tvu[(d0 + tid) * TVN_STR + nt * 8 + g];
            uint32_t b1 = tvu[(d0 + tid + 4) * TVN_STR + nt * 8 + g];
            mma_tf32(acc[nt], a0, a1, a2, a3, b0, b1);
        }
    }
    __syncthreads();                 // all xs reads done
    float* scratch = xs;             // reuse as [128][56] partial buffer
    if (warp >= 8) {
        #pragma unroll
        for (int nt = 0; nt < 7; nt++)
            #pragma unroll
            for (int c = 0; c < 4; c++) {
                int jj = j0 + g + ((c >= 2) ? 8 : 0);
                int k = nt * 8 + tid * 2 + (c & 1);
                scratch[jj * 56 + k] = acc[nt][c];
            }
    }
    __syncthreads();
    if (warp < 8) {
        #pragma unroll
        for (int nt = 0; nt < 7; nt++) {
            #pragma unroll
            for (int c = 0; c < 4; c++) {
                int jj = j0 + g + ((c >= 2) ? 8 : 0);
                int k = nt * 8 + tid * 2 + (c & 1);
                float full = acc[nt][c] + scratch[jj * 56 + k];
                if (k < KK) {
                    float tpn = full * rn[jj];
                    g_tpnT[(size_t)k * NROW + row0 + jj] = tpn;  // fallback copy
                    int bin = (int)(tpn * 128.0f);
                    if (bin >= 8) atomicAdd(&hloc[k * 128 + min(bin, 127)], 1);
                    if (bin >= 12) {                              // candidate
                        int ci = atomicAdd(&ccnt[k], 1);
                        if (ci < CBUF_W) cbuf[k * CBUF_W + ci] = tpn;
                        else {                                    // rare spill
                            int gi = atomicAdd(&g_candcnt[k], 1);
                            g_cand[(size_t)k * NROW + gi] = tpn;
                        }
                    }
                    if (tpn > 0.2985f) flg[jj] = 1.f;  // 1.5e-3 tf32 margin
                }
            }
        }
    }
    __syncthreads();
    if (t < 128 && flg[t] != 0.f) {
        int idx = atomicAdd(&g_nzcnt, 1);
        g_nzlist[idx] = row0 + t;
    }
    // bulk candidate flush: one atomic per concept
    if (t < KK) {
        int cnt = min(ccnt[t], CBUF_W);
        if (cnt > 0) {
            int base = atomicAdd(&g_candcnt[t], cnt);
            for (int i = 0; i < cnt; i++)
                g_cand[(size_t)t * NROW + base + i] = cbuf[t * CBUF_W + i];
        }
    }
    // tpnn zeros for all rows (flagged rows overwritten exactly by kernelRC)
    {
        float* tpnn = out + OUT_TPNN + (size_t)row0 * KK;
        for (int i = t; i < 128 * KK; i += 512) tpnn[i] = 0.f;
    }
    // flush histogram
    for (int i = t; i < KK * 128; i += 512) {
        int c = hloc[i];
        if (c) atomicAdd(&g_hist[i], c);
    }
}

// ===== kernelRC: blocks 0-127 exact sparse rows; 128-177 top-32 sums =====
__global__ void __launch_bounds__(256) kernelRC(const float* __restrict__ fin,
                                                const float* __restrict__ rec1,
                                                const float* __restrict__ rec2,
                                                float* __restrict__ out) {
    __shared__ float xrow[DD];
    __shared__ float msk[KK];
    __shared__ float nn[KK];
    __shared__ float r1[HH];
    __shared__ float red[256];
    __shared__ float inv_s;
    __shared__ int   hcnt[120];
    __shared__ int   s_bstar, scnt, sovf;
    __shared__ float svals[2048];
    __shared__ int   rarg[256];

    int t = threadIdx.x;
    if (blockIdx.x < 128) {
        // ---------------- kernelR: flagged rows, EXACT fp32 -------------
        int cnt = g_nzcnt;
        float* tpnn_out = out + OUT_TPNN;
        for (int i = blockIdx.x; i < cnt; i += 128) {
            int row = g_nzlist[i];
            int b = row >> 9, s = row & 511;
            float r = g_rnorm[row];
            xrow[t] = fin[(size_t)b * DD * SS + (size_t)t * SS + s];
            __syncthreads();
            if (t < KK) {
                float tp = 0.f;
                #pragma unroll 8
                for (int d = 0; d < DD; d++) tp += xrow[d] * g_tvn[d * KK + t];
                msk[t] = ((tp * r) > 0.3f) ? tp : 0.f;   // EXACT mask decision
            }
            __syncthreads();
            if (t == 0) {
                float su = 0.f;
                for (int k = 0; k < KK; k++) su += msk[k];
                inv_s = 1.0f / (su + 0.001f + 1e-8f);
            }
            __syncthreads();
            if (t < KK) {
                float v = msk[t] * inv_s;
                nn[t] = v;
                tpnn_out[(size_t)row * KK + t] = v;      // exact tpnn
            }
            __syncthreads();
            float z = 0.f;
            #pragma unroll 5
            for (int k = 0; k < KK; k++) z += nn[k] * rec1[k * HH + t];
            z = fmaxf(z, 0.f);
            r1[t] = z;
            atomicAdd(&g_hsum[b * HH + t], z);
            __syncthreads();
            float o = 0.f;
            #pragma unroll 8
            for (int h = 0; h < HH; h++) o += r1[h] * rec2[h * DD + t];
            float xn = xrow[t] * r;
            red[t] = o * o - 2.0f * xn * o;
            __syncthreads();
            for (int off = 128; off > 0; off >>= 1) {
                if (t < off) red[t] += red[t + off];
                __syncthreads();
            }
            if (t == 0) g_corr[row] = red[0];
            __syncthreads();
        }
        return;
    }

    // ---------------- finalC: bstar + filter + counting-rank top-32 -----
    int k = blockIdx.x - 128;
    if (t < 120) hcnt[t] = g_hist[k * 128 + 8 + t];
    if (t == 0) { scnt = 0; sovf = 0; }
    __syncthreads();
    if (t == 0) {
        int cum = 0, bstar = 7;
        for (int b = 127; b >= 8; b--) {
            cum += hcnt[b - 8];
            if (cum >= 32) { bstar = b; break; }
        }
        s_bstar = bstar;
    }
    __syncthreads();
    int bstar = s_bstar;
    int thr = bstar - 1;
    bool fast = (bstar != 7) && (thr >= 12);

    if (fast) {
        int C = g_candcnt[k];
        for (int i = t; i < C; i += 256) {
            float v = g_cand[(size_t)k * NROW + i];
            if ((int)(v * 128.0f) >= thr) {
                int idx = atomicAdd(&scnt, 1);
                if (idx < 2048) svals[idx] = v;
                else sovf = 1;
            }
        }
    }
    __syncthreads();
    if (fast && !sovf) {
        // counting-rank: sum values with rank < 32 (fully parallel)
        int C = scnt;
        float part = 0.f;
        for (int i = t; i < C; i += 256) {
            float v = svals[i];
            int rank = 0;
            for (int j = 0; j < C; j++) {
                float u = svals[j];
                rank += (u > v || (u == v && j < i)) ? 1 : 0;
            }
            if (rank < 32) part += v;
        }
        red[t] = part;
        __syncthreads();
        for (int off = 128; off > 0; off >>= 1) {
            if (t < off) red[t] += red[t + off];
            __syncthreads();
        }
        if (t == 0) g_topsum[k] = red[0];
    } else {
        // pathological fallback: destructive 32-round argmax over gmem column
        float* src = g_tpnT + (size_t)k * NROW;
        float sum = 0.f;
        for (int r = 0; r < 32; r++) {
            float m = -1e30f; int mi = -1;
            for (int i = t; i < NROW; i += 256) {
                float x = src[i];
                if (x > m) { m = x; mi = i; }
            }
            red[t] = m; rarg[t] = mi;
            __syncthreads();
            for (int off = 128; off > 0; off >>= 1) {
                if (t < off && red[t + off] > red[t]) {
                    red[t] = red[t + off]; rarg[t] = rarg[t + off];
                }
                __syncthreads();
            }
            if (t == 0) { sum += red[0]; src[rarg[0]] = -1e30f; }
            __syncthreads();
        }
        if (t == 0) g_topsum[k] = sum;
    }
}

// ===== kernelPF: blocks 0-127 pred head; block 128 ae + csim ============
__global__ void __launch_bounds__(256) kernelPF(const float* __restrict__ rec2,
                                                const float* __restrict__ Wc,
                                                const float* __restrict__ bc,
                                                float* __restrict__ out) {
    __shared__ float hs[HH];
    __shared__ float r0[256], r1[256];
    int t = threadIdx.x;
    if (blockIdx.x < 128) {
        int b = blockIdx.x;
        hs[t] = g_hsum[b * HH + t];
        __syncthreads();
        float acc = 0.f;
        #pragma unroll 8
        for (int h = 0; h < HH; h++) acc += hs[h] * rec2[h * DD + t];
        r0[t] = acc * Wc[t * 2];
        r1[t] = acc * Wc[t * 2 + 1];
        __syncthreads();
        for (int off = 128; off > 0; off >>= 1) {
            if (t < off) { r0[t] += r0[t + off]; r1[t] += r1[t + off]; }
            __syncthreads();
        }
        if (t == 0) {
            out[b * 2 + 0] = r0[0] * (1.0f / 512.0f) + bc[0];
            out[b * 2 + 1] = r1[0] * (1.0f / 512.0f) + bc[1];
        }
        return;
    }
    // block 128: ae + csim
    int cnt = g_nzcnt;
    float s = 0.f;
    for (int i = t; i < cnt; i += 256) s += g_corr[g_nzlist[i]];
    for (int i = t; i < 512; i += 256) s += g_aepartA[i];
    r0[t] = s;
    __syncthreads();
    for (int off = 128; off > 0; off >>= 1) {
        if (t < off) r0[t] += r0[t + off];
        __syncthreads();
    }
    if (t == 0) {
        out[OUT_AE] = r0[0] / 16777216.0f;
        float cs = 0.f;
        for (int k = 0; k < KK; k++) cs += g_topsum[k];
        out[OUT_CSIM] = -cs / 1600.0f;
    }
}

// ============================ launcher ===================================
extern "C" void kernel_launch(void* const* d_in, const int* in_sizes, int n_in,
                              void* d_out, int out_size) {
    const float* f_input      = (const float*)d_in[0];
    const float* topic_vector = (const float*)d_in[2];
    const float* rec1         = (const float*)d_in[3];
    const float* rec2         = (const float*)d_in[4];
    const float* Wc           = (const float*)d_in[5];
    const float* bc           = (const float*)d_in[6];
    float* out = (float*)d_out;

    cudaFuncSetAttribute(kernelA, cudaFuncAttributeMaxDynamicSharedMemorySize, A_SMEM_BYTES);

    prepAll<<<130, 256>>>(topic_vector, out);                  // idx 0
    kernelA<<<512, 512, A_SMEM_BYTES>>>(f_input, out);         // idx 1
    kernelRC<<<178, 256>>>(f_input, rec1, rec2, out);          // idx 2
    kernelPF<<<129, 256>>>(rec2, Wc, bc, out);                 // idx 3 -> profiled
}